// round 5
// baseline (speedup 1.0000x reference)
#include <cuda_runtime.h>
#include <math.h>

#define N_TOK 1024
#define Dm 512
#define Kf 128
#define Sq 512
#define DK 64

typedef unsigned long long ull;

// ---------------- packed f32x2 helpers --------------------------------------
__device__ __forceinline__ ull F2FMA(ull a, ull b, ull c) {
    ull r; asm("fma.rn.f32x2 %0, %1, %2, %3;" : "=l"(r) : "l"(a), "l"(b), "l"(c));
    return r;
}
__device__ __forceinline__ ull f2pack(float x, float y) {
    return (ull)__float_as_uint(x) | ((ull)__float_as_uint(y) << 32);
}
__device__ __forceinline__ float f2sum(ull v) {
    return __uint_as_float((unsigned)v) + __uint_as_float((unsigned)(v >> 32));
}
#define F2NEG1 0xBF800000BF800000ULL
#define F2ABSM 0x7FFFFFFF7FFFFFFFULL

// ---------------- scratch ---------------------------------------------------
__device__ float g_feat[(N_TOK + 4 * Dm) * Kf];
__device__ float g_R[N_TOK + 4 * Dm];
__device__ float g_Rcf[N_TOK];
__device__ float g_QKV[3 * N_TOK * Dm];
__device__ float g_scores[16 * Sq * Sq];
__device__ float g_ctx[N_TOK * Dm];
__device__ float g_cf[N_TOK * Kf];

// ---------------- fused feature GEMM: feat = [x;Pq;Pk;Pv;Po] @ omega --------
__global__ __launch_bounds__(256) void feat_gemm(
    const float* __restrict__ x,  const float* __restrict__ Pq,
    const float* __restrict__ Pk, const float* __restrict__ Pv,
    const float* __restrict__ Po, const float* __restrict__ omega,
    float* __restrict__ feat)
{
    __shared__ float As[32][68];
    __shared__ float Bs[32][68];
    int tx = threadIdx.x, ty = threadIdx.y;
    int tid = ty * 16 + tx;
    int bm = blockIdx.y * 64, bn = blockIdx.x * 64;

    const float* A;
    int row0;
    if (bm < N_TOK) { A = x; row0 = bm; }
    else {
        int s = (bm - N_TOK) >> 9;
        const float* Ps[4] = {Pq, Pk, Pv, Po};
        A = Ps[s]; row0 = (bm - N_TOK) & 511;
    }

    float acc[4][4] = {};
    for (int k0 = 0; k0 < Dm; k0 += 32) {
#pragma unroll
        for (int l = 0; l < 8; l++) {
            int e = tid + l * 256;
            int i = e >> 5, j = e & 31;
            As[j][i] = A[(size_t)(row0 + i) * Dm + k0 + j];
        }
#pragma unroll
        for (int l = 0; l < 8; l++) {
            int e = tid + l * 256;
            int kk = e >> 6, j = e & 63;
            Bs[kk][j] = omega[(size_t)(k0 + kk) * Kf + bn + j];
        }
        __syncthreads();
#pragma unroll
        for (int k = 0; k < 32; k++) {
            float4 a4 = *(const float4*)&As[k][ty * 4];
            float4 b4 = *(const float4*)&Bs[k][tx * 4];
            float av[4] = {a4.x, a4.y, a4.z, a4.w};
            float bv[4] = {b4.x, b4.y, b4.z, b4.w};
#pragma unroll
            for (int i = 0; i < 4; i++)
#pragma unroll
                for (int j = 0; j < 4; j++)
                    acc[i][j] = fmaf(av[i], bv[j], acc[i][j]);
        }
        __syncthreads();
    }
#pragma unroll
    for (int i = 0; i < 4; i++)
#pragma unroll
        for (int j = 0; j < 4; j++)
            feat[(size_t)(bm + ty * 4 + i) * Kf + bn + tx * 4 + j] = acc[i][j];
}

// ---------------- plain GEMM for ctx @ omega --------------------------------
__global__ __launch_bounds__(256) void gemm_nn(
    const float* __restrict__ A, const float* __restrict__ B,
    float* __restrict__ C, int M, int N, int K, int lda, int ldb, int ldc)
{
    __shared__ float As[32][68];
    __shared__ float Bs[32][68];
    int tx = threadIdx.x, ty = threadIdx.y;
    int tid = ty * 16 + tx;
    int bm = blockIdx.y * 64, bn = blockIdx.x * 64;
    float acc[4][4] = {};
    for (int k0 = 0; k0 < K; k0 += 32) {
#pragma unroll
        for (int l = 0; l < 8; l++) {
            int e = tid + l * 256;
            int i = e >> 5, j = e & 31;
            As[j][i] = A[(size_t)(bm + i) * lda + k0 + j];
        }
#pragma unroll
        for (int l = 0; l < 8; l++) {
            int e = tid + l * 256;
            int kk = e >> 6, j = e & 63;
            Bs[kk][j] = B[(size_t)(k0 + kk) * ldb + bn + j];
        }
        __syncthreads();
#pragma unroll
        for (int k = 0; k < 32; k++) {
            float4 a4 = *(const float4*)&As[k][ty * 4];
            float4 b4 = *(const float4*)&Bs[k][tx * 4];
            float av[4] = {a4.x, a4.y, a4.z, a4.w};
            float bv[4] = {b4.x, b4.y, b4.z, b4.w};
#pragma unroll
            for (int i = 0; i < 4; i++)
#pragma unroll
                for (int j = 0; j < 4; j++)
                    acc[i][j] = fmaf(av[i], bv[j], acc[i][j]);
        }
        __syncthreads();
    }
#pragma unroll
    for (int i = 0; i < 4; i++)
#pragma unroll
        for (int j = 0; j < 4; j++)
            C[(size_t)(bm + ty * 4 + i) * ldc + bn + tx * 4 + j] = acc[i][j];
}

// ---------------- row relu-sums ---------------------------------------------
__global__ __launch_bounds__(256) void rowrelu(const float* __restrict__ f,
                                               float* __restrict__ R)
{
    int row = blockIdx.x * 8 + threadIdx.y;
    int lane = threadIdx.x;
    float4 v = ((const float4*)(f + (size_t)row * Kf))[lane];
    float s = fmaxf(v.x, 0.f) + fmaxf(v.y, 0.f) + fmaxf(v.z, 0.f) + fmaxf(v.w, 0.f);
#pragma unroll
    for (int o = 16; o; o >>= 1) s += __shfl_xor_sync(0xffffffffu, s, o);
    if (lane == 0) R[row] = s;
}

// ---------------- Tversky 64x64 tile, f32x2, 6 planes, 256 threads ----------
// sim_k = th*ar*pr + ha*am*(p-|d|) + hb*pm*(a-|d|)
// out = acc - ha*Rx[i] - hb*Rp[j];  ar=relu(a), am=[a>0], d=a-p.
// Block 16x16, micro-tile 4 rows x 4 cols, k packed in pairs (u64).
__device__ __forceinline__ void tversky64(
    const float* __restrict__ xf, const float* __restrict__ pf,
    const float* __restrict__ Rx, const float* __restrict__ Rp,
    float th, float al, float be, int bn, int bo,
    float* __restrict__ out, int ldo)
{
    __shared__ ull sa[8][66], sA1[8][66], sA2[8][66];
    __shared__ ull sp[8][66], sPr[8][66], sB2[8][66];
    const float ha = 0.5f * al, hb = 0.5f * be;
    int tx = threadIdx.x, ty = threadIdx.y;      // 16 x 16
    int tid = ty * 16 + tx;                      // 0..255
    int fkk = tid & 7, fr = tid >> 3;            // fill: kk 0..7, row 0..31
    ull acc[4][4] = {};

    for (int c = 0; c < 8; c++) {                // chunks of 16 k (8 k2)
        int k0 = c * 16;
#pragma unroll
        for (int p = 0; p < 2; p++) {
            int r = fr + p * 32;
            float2 a2 = *(const float2*)&xf[(size_t)(bn + r) * Kf + k0 + 2 * fkk];
            sa [fkk][r] = f2pack(a2.x, a2.y);
            sA1[fkk][r] = f2pack(th * fmaxf(a2.x, 0.f), th * fmaxf(a2.y, 0.f));
            sA2[fkk][r] = f2pack(a2.x > 0.f ? ha : 0.f, a2.y > 0.f ? ha : 0.f);
            float2 p2 = *(const float2*)&pf[(size_t)(bo + r) * Kf + k0 + 2 * fkk];
            sp [fkk][r] = f2pack(p2.x, p2.y);
            sPr[fkk][r] = f2pack(fmaxf(p2.x, 0.f), fmaxf(p2.y, 0.f));
            sB2[fkk][r] = f2pack(p2.x > 0.f ? hb : 0.f, p2.y > 0.f ? hb : 0.f);
        }
        __syncthreads();
#pragma unroll
        for (int kk = 0; kk < 8; kk++) {
            ull ra[4], rA1[4], rA2[4], rp[4], rPr[4], rB2[4];
#pragma unroll
            for (int i = 0; i < 4; i += 2) {
                ulonglong2 t0 = *(const ulonglong2*)&sa [kk][ty * 4 + i];
                ra[i] = t0.x;  ra[i+1] = t0.y;
                ulonglong2 t1 = *(const ulonglong2*)&sA1[kk][ty * 4 + i];
                rA1[i] = t1.x; rA1[i+1] = t1.y;
                ulonglong2 t2 = *(const ulonglong2*)&sA2[kk][ty * 4 + i];
                rA2[i] = t2.x; rA2[i+1] = t2.y;
                ulonglong2 t3 = *(const ulonglong2*)&sp [kk][tx * 4 + i];
                rp[i] = t3.x;  rp[i+1] = t3.y;
                ulonglong2 t4 = *(const ulonglong2*)&sPr[kk][tx * 4 + i];
                rPr[i] = t4.x; rPr[i+1] = t4.y;
                ulonglong2 t5 = *(const ulonglong2*)&sB2[kk][tx * 4 + i];
                rB2[i] = t5.x; rB2[i+1] = t5.y;
            }
#pragma unroll
            for (int i = 0; i < 4; i++)
#pragma unroll
                for (int j = 0; j < 4; j++) {
                    ull d  = F2FMA(rp[j], F2NEG1, ra[i]);   // a - p
                    ull ad = d & F2ABSM;                    // |a - p|
                    ull u  = F2FMA(ad, F2NEG1, rp[j]);      // p - |d|
                    ull v  = F2FMA(ad, F2NEG1, ra[i]);      // a - |d|
                    ull t = acc[i][j];
                    t = F2FMA(rA1[i], rPr[j], t);
                    t = F2FMA(rA2[i], u, t);
                    t = F2FMA(rB2[j], v, t);
                    acc[i][j] = t;
                }
        }
        __syncthreads();
    }
    float rx[4], rpj[4];
#pragma unroll
    for (int i = 0; i < 4; i++) rx[i] = Rx[bn + ty * 4 + i];
#pragma unroll
    for (int j = 0; j < 4; j++) rpj[j] = Rp[bo + tx * 4 + j];
#pragma unroll
    for (int i = 0; i < 4; i++)
#pragma unroll
        for (int j = 0; j < 4; j++)
            out[(size_t)(bn + ty * 4 + i) * ldo + bo + tx * 4 + j] =
                f2sum(acc[i][j]) - ha * rx[i] - hb * rpj[j];
}

__global__ __launch_bounds__(256) void tversky_qkv(
    const float* __restrict__ feat, const float* __restrict__ R,
    const float* __restrict__ tab, float* __restrict__ qkv)
{
    int z = blockIdx.z;
    const float* pf = feat + (size_t)(N_TOK + z * Dm) * Kf;
    const float* Rp = R + N_TOK + z * Dm;
    const float* t3 = tab + z * 3;
    float* out = qkv + (size_t)z * N_TOK * Dm;
    tversky64(feat, pf, R, Rp, t3[0], t3[1], t3[2],
              blockIdx.y * 64, blockIdx.x * 64, out, Dm);
}

__global__ __launch_bounds__(256) void tversky_out(
    const float* __restrict__ cf, const float* __restrict__ Rcf,
    const float* __restrict__ feat, const float* __restrict__ R,
    const float* __restrict__ tab, float* __restrict__ out)
{
    const float* pf = feat + (size_t)(N_TOK + 3 * Dm) * Kf;
    const float* Rp = R + N_TOK + 3 * Dm;
    tversky64(cf, pf, Rcf, Rp, tab[9], tab[10], tab[11],
              blockIdx.y * 64, blockIdx.x * 64, out, Dm);
}

// ---------------- scores: 128x128 tile, 8x8 micro, fma-bound ----------------
__global__ __launch_bounds__(256) void scores_kernel(
    const float* __restrict__ Q, const float* __restrict__ Km,
    const int* __restrict__ mask, float* __restrict__ scores)
{
    __shared__ float Qs[16][136];   // [d][m]
    __shared__ float Ks[16][136];
    int z = blockIdx.z;
    int b = z >> 3, h = z & 7;
    const float* Qg = Q  + (size_t)b * Sq * Dm + h * DK;
    const float* Kg = Km + (size_t)b * Sq * Dm + h * DK;
    int bq = blockIdx.y * 128, bk = blockIdx.x * 128;
    int tx = threadIdx.x, ty = threadIdx.y;
    int tid = ty * 16 + tx;
    float acc[8][8] = {};
    for (int d0 = 0; d0 < DK; d0 += 16) {
#pragma unroll
        for (int l = 0; l < 8; l++) {
            int e = tid + l * 256;
            int m = e >> 4, d = e & 15;
            Qs[d][m] = Qg[(size_t)(bq + m) * Dm + d0 + d];
            Ks[d][m] = Kg[(size_t)(bk + m) * Dm + d0 + d];
        }
        __syncthreads();
#pragma unroll
        for (int d = 0; d < 16; d++) {
            float4 a0 = *(const float4*)&Qs[d][ty * 8];
            float4 a1 = *(const float4*)&Qs[d][ty * 8 + 4];
            float4 b0 = *(const float4*)&Ks[d][tx * 8];
            float4 b1 = *(const float4*)&Ks[d][tx * 8 + 4];
            float av[8] = {a0.x, a0.y, a0.z, a0.w, a1.x, a1.y, a1.z, a1.w};
            float bv[8] = {b0.x, b0.y, b0.z, b0.w, b1.x, b1.y, b1.z, b1.w};
#pragma unroll
            for (int i = 0; i < 8; i++)
#pragma unroll
                for (int j = 0; j < 8; j++)
                    acc[i][j] = fmaf(av[i], bv[j], acc[i][j]);
        }
        __syncthreads();
    }
    float* sout = scores + (size_t)z * Sq * Sq;
    const int* mg = mask + (size_t)b * Sq * Sq;
#pragma unroll
    for (int i = 0; i < 8; i++)
#pragma unroll
        for (int j = 0; j < 8; j++) {
            int q = bq + ty * 8 + i, kk = bk + tx * 8 + j;
            float s = acc[i][j] * 0.125f;
            if (mg[(size_t)q * Sq + kk] == 0) s = -INFINITY;
            sout[(size_t)q * Sq + kk] = s;
        }
}

// ---------------- row softmax over 512 --------------------------------------
__global__ __launch_bounds__(128) void softmax_kernel(float* __restrict__ scores)
{
    __shared__ float red_m[4], red_s[4];
    size_t row = blockIdx.x;
    float* r = scores + row * Sq;
    int t = threadIdx.x;
    float v0 = r[t], v1 = r[t + 128], v2 = r[t + 256], v3 = r[t + 384];
    float m = fmaxf(fmaxf(v0, v1), fmaxf(v2, v3));
#pragma unroll
    for (int o = 16; o; o >>= 1) m = fmaxf(m, __shfl_xor_sync(0xffffffffu, m, o));
    if ((t & 31) == 0) red_m[t >> 5] = m;
    __syncthreads();
    m = fmaxf(fmaxf(red_m[0], red_m[1]), fmaxf(red_m[2], red_m[3]));
    float e0 = expf(v0 - m), e1 = expf(v1 - m), e2 = expf(v2 - m), e3 = expf(v3 - m);
    float s = e0 + e1 + e2 + e3;
#pragma unroll
    for (int o = 16; o; o >>= 1) s += __shfl_xor_sync(0xffffffffu, s, o);
    if ((t & 31) == 0) red_s[t >> 5] = s;
    __syncthreads();
    s = red_s[0] + red_s[1] + red_s[2] + red_s[3];
    float inv = 1.f / s;
    r[t]       = e0 * inv;
    r[t + 128] = e1 * inv;
    r[t + 256] = e2 * inv;
    r[t + 384] = e3 * inv;
}

// ---------------- ctx = attn @ V (per head, scalar) -------------------------
__global__ __launch_bounds__(256) void ctx_kernel(
    const float* __restrict__ scores, const float* __restrict__ V,
    float* __restrict__ ctx)
{
    __shared__ float As[32][68];   // [k][q]
    __shared__ float Bs[32][68];   // [k][d]
    int z = blockIdx.z;
    int b = z >> 3, h = z & 7;
    const float* Ag = scores + (size_t)z * Sq * Sq;
    const float* Vg = V + (size_t)b * Sq * Dm + h * DK;
    int bq = blockIdx.y * 64;
    int tx = threadIdx.x, ty = threadIdx.y;
    int tid = ty * 16 + tx;
    float acc[4][4] = {};
    for (int k0 = 0; k0 < Sq; k0 += 32) {
#pragma unroll
        for (int l = 0; l < 8; l++) {
            int e = tid + l * 256;
            int q = e >> 5, kk = e & 31;
            As[kk][q] = Ag[(size_t)(bq + q) * Sq + k0 + kk];
        }
#pragma unroll
        for (int l = 0; l < 8; l++) {
            int e = tid + l * 256;
            int kk = e >> 6, d = e & 63;
            Bs[kk][d] = Vg[(size_t)(k0 + kk) * Dm + d];
        }
        __syncthreads();
#pragma unroll
        for (int k = 0; k < 32; k++) {
            float4 a4 = *(const float4*)&As[k][ty * 4];
            float4 b4 = *(const float4*)&Bs[k][tx * 4];
            float av[4] = {a4.x, a4.y, a4.z, a4.w};
            float bv[4] = {b4.x, b4.y, b4.z, b4.w};
#pragma unroll
            for (int i = 0; i < 4; i++)
#pragma unroll
                for (int j = 0; j < 4; j++)
                    acc[i][j] = fmaf(av[i], bv[j], acc[i][j]);
        }
        __syncthreads();
    }
    float* cg = ctx + (size_t)b * Sq * Dm + h * DK;
#pragma unroll
    for (int i = 0; i < 4; i++)
#pragma unroll
        for (int j = 0; j < 4; j++)
            cg[(size_t)(bq + ty * 4 + i) * Dm + tx * 4 + j] = acc[i][j];
}

// ---------------- launch ----------------------------------------------------
extern "C" void kernel_launch(void* const* d_in, const int* in_sizes, int n_in,
                              void* d_out, int out_size)
{
    const float* x     = (const float*)d_in[0];
    const int*   mask  = (const int*)d_in[1];
    const float* omega = (const float*)d_in[2];
    const float* Pq    = (const float*)d_in[3];
    const float* Pk    = (const float*)d_in[4];
    const float* Pv    = (const float*)d_in[5];
    const float* Po    = (const float*)d_in[6];
    const float* tab   = (const float*)d_in[7];
    float* out = (float*)d_out;

    float *p_feat, *p_R, *p_Rcf, *p_qkv, *p_sc, *p_ctx, *p_cf;
    cudaGetSymbolAddress((void**)&p_feat, g_feat);
    cudaGetSymbolAddress((void**)&p_R, g_R);
    cudaGetSymbolAddress((void**)&p_Rcf, g_Rcf);
    cudaGetSymbolAddress((void**)&p_qkv, g_QKV);
    cudaGetSymbolAddress((void**)&p_sc, g_scores);
    cudaGetSymbolAddress((void**)&p_ctx, g_ctx);
    cudaGetSymbolAddress((void**)&p_cf, g_cf);

    float* p_Q = p_qkv;
    float* p_K = p_qkv + (size_t)N_TOK * Dm;
    float* p_V = p_qkv + (size_t)2 * N_TOK * Dm;

    dim3 blk(16, 16);

    // feature maps + row relu-sums
    feat_gemm<<<dim3(2, 48), blk>>>(x, Pq, Pk, Pv, Po, omega, p_feat);
    rowrelu<<<(N_TOK + 4 * Dm) / 8, dim3(32, 8)>>>(p_feat, p_R);

    // Q, K, V projections
    tversky_qkv<<<dim3(8, 16, 3), blk>>>(p_feat, p_R, tab, p_qkv);

    // attention
    scores_kernel<<<dim3(4, 4, 16), blk>>>(p_Q, p_K, mask, p_sc);
    softmax_kernel<<<16 * Sq, 128>>>(p_sc);
    ctx_kernel<<<dim3(1, 8, 16), blk>>>(p_sc, p_V, p_ctx);

    // output projection
    gemm_nn<<<dim3(2, 16), blk>>>(p_ctx, omega, p_cf, N_TOK, Kf, Dm, Dm, Kf, Kf);
    rowrelu<<<N_TOK / 8, dim3(32, 8)>>>(p_cf, p_Rcf);
    tversky_out<<<dim3(8, 16), blk>>>(p_cf, p_Rcf, p_feat, p_R, tab, out);
}

// round 6
// speedup vs baseline: 1.0675x; 1.0675x over previous
#include <cuda_runtime.h>
#include <math.h>

#define N_TOK 1024
#define Dm 512
#define Kf 128
#define Sq 512
#define DK 64

// ---------------- scratch ---------------------------------------------------
__device__ float g_feat[(N_TOK + 4 * Dm) * Kf];
__device__ float g_QKV[3 * N_TOK * Dm];
__device__ float g_probs[16 * Sq * Sq];
__device__ float g_ctx[N_TOK * Dm];
__device__ float g_cf[N_TOK * Kf];

// ---------------- fused feature GEMM: feat = [x;Pq;Pk;Pv;Po] @ omega --------
__global__ __launch_bounds__(256) void feat_gemm(
    const float* __restrict__ x,  const float* __restrict__ Pq,
    const float* __restrict__ Pk, const float* __restrict__ Pv,
    const float* __restrict__ Po, const float* __restrict__ omega,
    float* __restrict__ feat)
{
    __shared__ float As[32][68];
    __shared__ float Bs[32][68];
    int tx = threadIdx.x, ty = threadIdx.y;
    int tid = ty * 16 + tx;
    int bm = blockIdx.y * 64, bn = blockIdx.x * 64;

    const float* A;
    int row0;
    if (bm < N_TOK) { A = x; row0 = bm; }
    else {
        int s = (bm - N_TOK) >> 9;
        const float* Ps[4] = {Pq, Pk, Pv, Po};
        A = Ps[s]; row0 = (bm - N_TOK) & 511;
    }

    float acc[4][4] = {};
    for (int k0 = 0; k0 < Dm; k0 += 32) {
#pragma unroll
        for (int l = 0; l < 8; l++) {
            int e = tid + l * 256;
            int i = e >> 5, j = e & 31;
            As[j][i] = A[(size_t)(row0 + i) * Dm + k0 + j];
        }
#pragma unroll
        for (int l = 0; l < 8; l++) {
            int e = tid + l * 256;
            int kk = e >> 6, j = e & 63;
            Bs[kk][j] = omega[(size_t)(k0 + kk) * Kf + bn + j];
        }
        __syncthreads();
#pragma unroll
        for (int k = 0; k < 32; k++) {
            float4 a4 = *(const float4*)&As[k][ty * 4];
            float4 b4 = *(const float4*)&Bs[k][tx * 4];
            float av[4] = {a4.x, a4.y, a4.z, a4.w};
            float bv[4] = {b4.x, b4.y, b4.z, b4.w};
#pragma unroll
            for (int i = 0; i < 4; i++)
#pragma unroll
                for (int j = 0; j < 4; j++)
                    acc[i][j] = fmaf(av[i], bv[j], acc[i][j]);
        }
        __syncthreads();
    }
#pragma unroll
    for (int i = 0; i < 4; i++)
#pragma unroll
        for (int j = 0; j < 4; j++)
            feat[(size_t)(bm + ty * 4 + i) * Kf + bn + tx * 4 + j] = acc[i][j];
}

// ---------------- plain GEMM for ctx @ omega --------------------------------
__global__ __launch_bounds__(256) void gemm_nn(
    const float* __restrict__ A, const float* __restrict__ B,
    float* __restrict__ C, int M, int N, int K, int lda, int ldb, int ldc)
{
    __shared__ float As[32][68];
    __shared__ float Bs[32][68];
    int tx = threadIdx.x, ty = threadIdx.y;
    int tid = ty * 16 + tx;
    int bm = blockIdx.y * 64, bn = blockIdx.x * 64;
    float acc[4][4] = {};
    for (int k0 = 0; k0 < K; k0 += 32) {
#pragma unroll
        for (int l = 0; l < 8; l++) {
            int e = tid + l * 256;
            int i = e >> 5, j = e & 31;
            As[j][i] = A[(size_t)(bm + i) * lda + k0 + j];
        }
#pragma unroll
        for (int l = 0; l < 8; l++) {
            int e = tid + l * 256;
            int kk = e >> 6, j = e & 63;
            Bs[kk][j] = B[(size_t)(k0 + kk) * ldb + bn + j];
        }
        __syncthreads();
#pragma unroll
        for (int k = 0; k < 32; k++) {
            float4 a4 = *(const float4*)&As[k][ty * 4];
            float4 b4 = *(const float4*)&Bs[k][tx * 4];
            float av[4] = {a4.x, a4.y, a4.z, a4.w};
            float bv[4] = {b4.x, b4.y, b4.z, b4.w};
#pragma unroll
            for (int i = 0; i < 4; i++)
#pragma unroll
                for (int j = 0; j < 4; j++)
                    acc[i][j] = fmaf(av[i], bv[j], acc[i][j]);
        }
        __syncthreads();
    }
#pragma unroll
    for (int i = 0; i < 4; i++)
#pragma unroll
        for (int j = 0; j < 4; j++)
            C[(size_t)(bm + ty * 4 + i) * ldc + bn + tx * 4 + j] = acc[i][j];
}

// ---------------- Tversky similarity tile (scalar, R2-proven) ---------------
__device__ __forceinline__ void tversky_tile(
    const float* __restrict__ xf, const float* __restrict__ pf,
    float th, float al, float be, int bn, int bo,
    float* __restrict__ out, int ldo)
{
    __shared__ float sxa[16][68], sxp[16][68], sxm[16][68];
    __shared__ float spa[16][68], spt[16][68], spb[16][68];
    int tx = threadIdx.x, ty = threadIdx.y;
    int tid = ty * 16 + tx;
    float acc[4][4] = {};
    for (int k0 = 0; k0 < Kf; k0 += 16) {
#pragma unroll
        for (int l = 0; l < 4; l++) {
            int e = tid + l * 256;
            int i = e >> 4, j = e & 15;
            float a = xf[(size_t)(bn + i) * Kf + k0 + j];
            sxa[j][i] = a;
            sxp[j][i] = fmaxf(a, 0.f);
            sxm[j][i] = (a > 0.f) ? -al : 0.f;
            float p = pf[(size_t)(bo + i) * Kf + k0 + j];
            spa[j][i] = p;
            spt[j][i] = th * fmaxf(p, 0.f);
            spb[j][i] = (p > 0.f) ? -be : 0.f;
        }
        __syncthreads();
#pragma unroll
        for (int k = 0; k < 16; k++) {
            float4 a4  = *(const float4*)&sxa[k][ty * 4];
            float4 ap4 = *(const float4*)&sxp[k][ty * 4];
            float4 am4 = *(const float4*)&sxm[k][ty * 4];
            float4 p4  = *(const float4*)&spa[k][tx * 4];
            float4 tp4 = *(const float4*)&spt[k][tx * 4];
            float4 pb4 = *(const float4*)&spb[k][tx * 4];
            float av[4]  = {a4.x, a4.y, a4.z, a4.w};
            float apv[4] = {ap4.x, ap4.y, ap4.z, ap4.w};
            float amv[4] = {am4.x, am4.y, am4.z, am4.w};
            float pv[4]  = {p4.x, p4.y, p4.z, p4.w};
            float tpv[4] = {tp4.x, tp4.y, tp4.z, tp4.w};
            float pbv[4] = {pb4.x, pb4.y, pb4.z, pb4.w};
#pragma unroll
            for (int i = 0; i < 4; i++)
#pragma unroll
                for (int j = 0; j < 4; j++) {
                    float d   = av[i] - pv[j];
                    float dab = fmaxf(d, 0.f);
                    float dba = dab - d;
                    float t = acc[i][j];
                    t = fmaf(apv[i], tpv[j], t);
                    t = fmaf(amv[i], dab, t);
                    t = fmaf(pbv[j], dba, t);
                    acc[i][j] = t;
                }
        }
        __syncthreads();
    }
#pragma unroll
    for (int i = 0; i < 4; i++)
#pragma unroll
        for (int j = 0; j < 4; j++)
            out[(size_t)(bn + ty * 4 + i) * ldo + bo + tx * 4 + j] = acc[i][j];
}

__global__ __launch_bounds__(256) void tversky_qkv(
    const float* __restrict__ feat, const float* __restrict__ tab,
    float* __restrict__ qkv)
{
    int z = blockIdx.z;
    const float* pf = feat + (size_t)(N_TOK + z * Dm) * Kf;
    const float* t3 = tab + z * 3;
    float* out = qkv + (size_t)z * N_TOK * Dm;
    tversky_tile(feat, pf, t3[0], t3[1], t3[2],
                 blockIdx.y * 64, blockIdx.x * 64, out, Dm);
}

__global__ __launch_bounds__(256) void tversky_out(
    const float* __restrict__ cf, const float* __restrict__ feat,
    const float* __restrict__ tab, float* __restrict__ out)
{
    const float* pf = feat + (size_t)(N_TOK + 3 * Dm) * Kf;
    tversky_tile(cf, pf, tab[9], tab[10], tab[11],
                 blockIdx.y * 64, blockIdx.x * 64, out, Dm);
}

// ---------------- fused scores + mask + softmax ------------------------------
// Block: 256 threads (16x16). q-tile = 32 (ty -> 2 rows), full k row (512)
// resident in registers: acc[2][32], col = kc*64 + tx*4 + j.
// Grid: (16 q-tiles, 16 z).
__global__ __launch_bounds__(256) void scores_softmax(
    const float* __restrict__ Q, const float* __restrict__ Km,
    const int* __restrict__ mask, float* __restrict__ probs)
{
    __shared__ float Qs[64][36];   // [d][q]
    __shared__ float Ks[64][68];   // [d][kk]
    int z = blockIdx.y;
    int b = z >> 3, h = z & 7;
    const float* Qg = Q  + (size_t)b * Sq * Dm + h * DK;
    const float* Kg = Km + (size_t)b * Sq * Dm + h * DK;
    int bq = blockIdx.x * 32;
    int tx = threadIdx.x, ty = threadIdx.y;
    int tid = ty * 16 + tx;

#pragma unroll
    for (int l = 0; l < 8; l++) {          // Qs: 32q x 64d
        int e = tid + l * 256;
        int m = e >> 6, d = e & 63;
        Qs[d][m] = Qg[(size_t)(bq + m) * Dm + d];
    }

    float acc[2][32];
#pragma unroll
    for (int s = 0; s < 2; s++)
#pragma unroll
        for (int c = 0; c < 32; c++) acc[s][c] = 0.f;

    for (int kc = 0; kc < 8; kc++) {
        int bk = kc * 64;
#pragma unroll
        for (int l = 0; l < 16; l++) {     // Ks: 64k x 64d
            int e = tid + l * 256;
            int kk = e >> 6, d = e & 63;
            Ks[d][kk] = Kg[(size_t)(bk + kk) * Dm + d];
        }
        __syncthreads();
#pragma unroll
        for (int d = 0; d < 64; d++) {
            float a0 = Qs[d][ty * 2];
            float a1 = Qs[d][ty * 2 + 1];
            float4 b4 = *(const float4*)&Ks[d][tx * 4];
            acc[0][kc*4+0] = fmaf(a0, b4.x, acc[0][kc*4+0]);
            acc[0][kc*4+1] = fmaf(a0, b4.y, acc[0][kc*4+1]);
            acc[0][kc*4+2] = fmaf(a0, b4.z, acc[0][kc*4+2]);
            acc[0][kc*4+3] = fmaf(a0, b4.w, acc[0][kc*4+3]);
            acc[1][kc*4+0] = fmaf(a1, b4.x, acc[1][kc*4+0]);
            acc[1][kc*4+1] = fmaf(a1, b4.y, acc[1][kc*4+1]);
            acc[1][kc*4+2] = fmaf(a1, b4.z, acc[1][kc*4+2]);
            acc[1][kc*4+3] = fmaf(a1, b4.w, acc[1][kc*4+3]);
        }
        __syncthreads();
    }

    // mask: -inf where mask == 0
    const int* mg = mask + (size_t)b * Sq * Sq;
#pragma unroll
    for (int s = 0; s < 2; s++) {
        int row = bq + ty * 2 + s;
#pragma unroll
        for (int kc = 0; kc < 8; kc++) {
            int4 m4 = *(const int4*)&mg[(size_t)row * Sq + kc * 64 + tx * 4];
            if (m4.x == 0) acc[s][kc*4+0] = -INFINITY;
            if (m4.y == 0) acc[s][kc*4+1] = -INFINITY;
            if (m4.z == 0) acc[s][kc*4+2] = -INFINITY;
            if (m4.w == 0) acc[s][kc*4+3] = -INFINITY;
        }
    }

    // row max (local then across 16 tx lanes; same-warp half)
    float m0 = -INFINITY, m1 = -INFINITY;
#pragma unroll
    for (int c = 0; c < 32; c++) {
        m0 = fmaxf(m0, acc[0][c]);
        m1 = fmaxf(m1, acc[1][c]);
    }
#pragma unroll
    for (int o = 8; o; o >>= 1) {
        m0 = fmaxf(m0, __shfl_xor_sync(0xffffffffu, m0, o));
        m1 = fmaxf(m1, __shfl_xor_sync(0xffffffffu, m1, o));
    }

    // exp((a - m) / 8) and row sums
    float s0 = 0.f, s1 = 0.f;
#pragma unroll
    for (int c = 0; c < 32; c++) {
        float e0 = __expf((acc[0][c] - m0) * 0.125f);
        float e1 = __expf((acc[1][c] - m1) * 0.125f);
        acc[0][c] = e0; s0 += e0;
        acc[1][c] = e1; s1 += e1;
    }
#pragma unroll
    for (int o = 8; o; o >>= 1) {
        s0 += __shfl_xor_sync(0xffffffffu, s0, o);
        s1 += __shfl_xor_sync(0xffffffffu, s1, o);
    }
    float i0 = 1.f / s0, i1 = 1.f / s1;

    float* pout = probs + (size_t)z * Sq * Sq;
#pragma unroll
    for (int kc = 0; kc < 8; kc++) {
        float4 w0 = make_float4(acc[0][kc*4+0]*i0, acc[0][kc*4+1]*i0,
                                acc[0][kc*4+2]*i0, acc[0][kc*4+3]*i0);
        float4 w1 = make_float4(acc[1][kc*4+0]*i1, acc[1][kc*4+1]*i1,
                                acc[1][kc*4+2]*i1, acc[1][kc*4+3]*i1);
        *(float4*)&pout[(size_t)(bq + ty*2)     * Sq + kc*64 + tx*4] = w0;
        *(float4*)&pout[(size_t)(bq + ty*2 + 1) * Sq + kc*64 + tx*4] = w1;
    }
}

// ---------------- ctx = attn @ V (per head, scalar) -------------------------
__global__ __launch_bounds__(256) void ctx_kernel(
    const float* __restrict__ probs, const float* __restrict__ V,
    float* __restrict__ ctx)
{
    __shared__ float As[32][68];   // [k][q]
    __shared__ float Bs[32][68];   // [k][d]
    int z = blockIdx.z;
    int b = z >> 3, h = z & 7;
    const float* Ag = probs + (size_t)z * Sq * Sq;
    const float* Vg = V + (size_t)b * Sq * Dm + h * DK;
    int bq = blockIdx.y * 64;
    int tx = threadIdx.x, ty = threadIdx.y;
    int tid = ty * 16 + tx;
    float acc[4][4] = {};
    for (int k0 = 0; k0 < Sq; k0 += 32) {
#pragma unroll
        for (int l = 0; l < 8; l++) {
            int e = tid + l * 256;
            int q = e >> 5, kk = e & 31;
            As[kk][q] = Ag[(size_t)(bq + q) * Sq + k0 + kk];
        }
#pragma unroll
        for (int l = 0; l < 8; l++) {
            int e = tid + l * 256;
            int kk = e >> 6, d = e & 63;
            Bs[kk][d] = Vg[(size_t)(k0 + kk) * Dm + d];
        }
        __syncthreads();
#pragma unroll
        for (int k = 0; k < 32; k++) {
            float4 a4 = *(const float4*)&As[k][ty * 4];
            float4 b4 = *(const float4*)&Bs[k][tx * 4];
            float av[4] = {a4.x, a4.y, a4.z, a4.w};
            float bv[4] = {b4.x, b4.y, b4.z, b4.w};
#pragma unroll
            for (int i = 0; i < 4; i++)
#pragma unroll
                for (int j = 0; j < 4; j++)
                    acc[i][j] = fmaf(av[i], bv[j], acc[i][j]);
        }
        __syncthreads();
    }
    float* cg = ctx + (size_t)b * Sq * Dm + h * DK;
#pragma unroll
    for (int i = 0; i < 4; i++)
#pragma unroll
        for (int j = 0; j < 4; j++)
            cg[(size_t)(bq + ty * 4 + i) * Dm + tx * 4 + j] = acc[i][j];
}

// ---------------- launch ----------------------------------------------------
extern "C" void kernel_launch(void* const* d_in, const int* in_sizes, int n_in,
                              void* d_out, int out_size)
{
    const float* x     = (const float*)d_in[0];
    const int*   mask  = (const int*)d_in[1];
    const float* omega = (const float*)d_in[2];
    const float* Pq    = (const float*)d_in[3];
    const float* Pk    = (const float*)d_in[4];
    const float* Pv    = (const float*)d_in[5];
    const float* Po    = (const float*)d_in[6];
    const float* tab   = (const float*)d_in[7];
    float* out = (float*)d_out;

    float *p_feat, *p_qkv, *p_pr, *p_ctx, *p_cf;
    cudaGetSymbolAddress((void**)&p_feat, g_feat);
    cudaGetSymbolAddress((void**)&p_qkv, g_QKV);
    cudaGetSymbolAddress((void**)&p_pr, g_probs);
    cudaGetSymbolAddress((void**)&p_ctx, g_ctx);
    cudaGetSymbolAddress((void**)&p_cf, g_cf);

    float* p_Q = p_qkv;
    float* p_K = p_qkv + (size_t)N_TOK * Dm;
    float* p_V = p_qkv + (size_t)2 * N_TOK * Dm;

    dim3 blk(16, 16);

    // feature maps
    feat_gemm<<<dim3(2, 48), blk>>>(x, Pq, Pk, Pv, Po, omega, p_feat);

    // Q, K, V projections
    tversky_qkv<<<dim3(8, 16, 3), blk>>>(p_feat, tab, p_qkv);

    // attention (fused scores + mask + softmax)
    scores_softmax<<<dim3(16, 16), blk>>>(p_Q, p_K, mask, p_pr);
    ctx_kernel<<<dim3(1, 8, 16), blk>>>(p_pr, p_V, p_ctx);

    // output projection
    gemm_nn<<<dim3(2, 16), blk>>>(p_ctx, omega, p_cf, N_TOK, Kf, Dm, Dm, Kf, Kf);
    tversky_out<<<dim3(8, 16), blk>>>(p_cf, p_feat, tab, out);
}

// round 7
// speedup vs baseline: 1.1662x; 1.0925x over previous
#include <cuda_runtime.h>
#include <math.h>

#define N_TOK 1024
#define Dm 512
#define Kf 128
#define Sq 512
#define DK 64

// ---------------- scratch ---------------------------------------------------
__device__ float g_feat[(N_TOK + 4 * Dm) * Kf];
__device__ float g_QKV[3 * N_TOK * Dm];
__device__ float g_ctx[N_TOK * Dm];
__device__ float g_cfp[4][N_TOK * Kf];   // split-K partials of ctx @ omega
__device__ float g_cf[N_TOK * Kf];

// ---------------- fused feature GEMM: feat = [x;Pq;Pk;Pv;Po] @ omega --------
__global__ __launch_bounds__(256) void feat_gemm(
    const float* __restrict__ x,  const float* __restrict__ Pq,
    const float* __restrict__ Pk, const float* __restrict__ Pv,
    const float* __restrict__ Po, const float* __restrict__ omega,
    float* __restrict__ feat)
{
    __shared__ float As[32][68];
    __shared__ float Bs[32][68];
    int tx = threadIdx.x, ty = threadIdx.y;
    int tid = ty * 16 + tx;
    int bm = blockIdx.y * 64, bn = blockIdx.x * 64;

    const float* A;
    int row0;
    if (bm < N_TOK) { A = x; row0 = bm; }
    else {
        int s = (bm - N_TOK) >> 9;
        const float* Ps[4] = {Pq, Pk, Pv, Po};
        A = Ps[s]; row0 = (bm - N_TOK) & 511;
    }

    float acc[4][4] = {};
    for (int k0 = 0; k0 < Dm; k0 += 32) {
#pragma unroll
        for (int l = 0; l < 8; l++) {
            int e = tid + l * 256;
            int i = e >> 5, j = e & 31;
            As[j][i] = A[(size_t)(row0 + i) * Dm + k0 + j];
        }
#pragma unroll
        for (int l = 0; l < 8; l++) {
            int e = tid + l * 256;
            int kk = e >> 6, j = e & 63;
            Bs[kk][j] = omega[(size_t)(k0 + kk) * Kf + bn + j];
        }
        __syncthreads();
#pragma unroll
        for (int k = 0; k < 32; k++) {
            float4 a4 = *(const float4*)&As[k][ty * 4];
            float4 b4 = *(const float4*)&Bs[k][tx * 4];
            float av[4] = {a4.x, a4.y, a4.z, a4.w};
            float bv[4] = {b4.x, b4.y, b4.z, b4.w};
#pragma unroll
            for (int i = 0; i < 4; i++)
#pragma unroll
                for (int j = 0; j < 4; j++)
                    acc[i][j] = fmaf(av[i], bv[j], acc[i][j]);
        }
        __syncthreads();
    }
#pragma unroll
    for (int i = 0; i < 4; i++)
#pragma unroll
        for (int j = 0; j < 4; j++)
            feat[(size_t)(bm + ty * 4 + i) * Kf + bn + tx * 4 + j] = acc[i][j];
}

// ---------------- split-K GEMM: cfp[z] = ctx @ omega over k-chunk z ---------
__global__ __launch_bounds__(256) void gemm_split(
    const float* __restrict__ A, const float* __restrict__ B,
    float* __restrict__ Cp)
{
    __shared__ float As[32][68];
    __shared__ float Bs[32][68];
    int tx = threadIdx.x, ty = threadIdx.y;
    int tid = ty * 16 + tx;
    int bm = blockIdx.y * 64, bn = blockIdx.x * 64;
    int kbase = blockIdx.z * 128;
    float* C = Cp + (size_t)blockIdx.z * N_TOK * Kf;
    float acc[4][4] = {};
    for (int k0 = kbase; k0 < kbase + 128; k0 += 32) {
#pragma unroll
        for (int l = 0; l < 8; l++) {
            int e = tid + l * 256;
            int i = e >> 5, j = e & 31;
            As[j][i] = A[(size_t)(bm + i) * Dm + k0 + j];
        }
#pragma unroll
        for (int l = 0; l < 8; l++) {
            int e = tid + l * 256;
            int kk = e >> 6, j = e & 63;
            Bs[kk][j] = B[(size_t)(k0 + kk) * Kf + bn + j];
        }
        __syncthreads();
#pragma unroll
        for (int k = 0; k < 32; k++) {
            float4 a4 = *(const float4*)&As[k][ty * 4];
            float4 b4 = *(const float4*)&Bs[k][tx * 4];
            float av[4] = {a4.x, a4.y, a4.z, a4.w};
            float bv[4] = {b4.x, b4.y, b4.z, b4.w};
#pragma unroll
            for (int i = 0; i < 4; i++)
#pragma unroll
                for (int j = 0; j < 4; j++)
                    acc[i][j] = fmaf(av[i], bv[j], acc[i][j]);
        }
        __syncthreads();
    }
#pragma unroll
    for (int i = 0; i < 4; i++)
#pragma unroll
        for (int j = 0; j < 4; j++)
            C[(size_t)(bm + ty * 4 + i) * Kf + bn + tx * 4 + j] = acc[i][j];
}

__global__ __launch_bounds__(256) void add4(const float* __restrict__ Cp,
                                            float* __restrict__ C)
{
    int idx = blockIdx.x * 256 + threadIdx.x;      // float4 index
    const size_t n = (size_t)N_TOK * Kf;
    float4 a = ((const float4*)(Cp + 0 * n))[idx];
    float4 b = ((const float4*)(Cp + 1 * n))[idx];
    float4 c = ((const float4*)(Cp + 2 * n))[idx];
    float4 d = ((const float4*)(Cp + 3 * n))[idx];
    ((float4*)C)[idx] = make_float4(a.x + b.x + c.x + d.x,
                                    a.y + b.y + c.y + d.y,
                                    a.z + b.z + c.z + d.z,
                                    a.w + b.w + c.w + d.w);
}

// ---------------- Tversky 64x64 tile (scalar, R2-proven) --------------------
__device__ __forceinline__ void tversky_tile(
    const float* __restrict__ xf, const float* __restrict__ pf,
    float th, float al, float be, int bn, int bo,
    float* __restrict__ out, int ldo)
{
    __shared__ float sxa[16][68], sxp[16][68], sxm[16][68];
    __shared__ float spa[16][68], spt[16][68], spb[16][68];
    int tx = threadIdx.x, ty = threadIdx.y;
    int tid = ty * 16 + tx;
    float acc[4][4] = {};
    for (int k0 = 0; k0 < Kf; k0 += 16) {
#pragma unroll
        for (int l = 0; l < 4; l++) {
            int e = tid + l * 256;
            int i = e >> 4, j = e & 15;
            float a = xf[(size_t)(bn + i) * Kf + k0 + j];
            sxa[j][i] = a;
            sxp[j][i] = fmaxf(a, 0.f);
            sxm[j][i] = (a > 0.f) ? -al : 0.f;
            float p = pf[(size_t)(bo + i) * Kf + k0 + j];
            spa[j][i] = p;
            spt[j][i] = th * fmaxf(p, 0.f);
            spb[j][i] = (p > 0.f) ? -be : 0.f;
        }
        __syncthreads();
#pragma unroll
        for (int k = 0; k < 16; k++) {
            float4 a4  = *(const float4*)&sxa[k][ty * 4];
            float4 ap4 = *(const float4*)&sxp[k][ty * 4];
            float4 am4 = *(const float4*)&sxm[k][ty * 4];
            float4 p4  = *(const float4*)&spa[k][tx * 4];
            float4 tp4 = *(const float4*)&spt[k][tx * 4];
            float4 pb4 = *(const float4*)&spb[k][tx * 4];
            float av[4]  = {a4.x, a4.y, a4.z, a4.w};
            float apv[4] = {ap4.x, ap4.y, ap4.z, ap4.w};
            float amv[4] = {am4.x, am4.y, am4.z, am4.w};
            float pv[4]  = {p4.x, p4.y, p4.z, p4.w};
            float tpv[4] = {tp4.x, tp4.y, tp4.z, tp4.w};
            float pbv[4] = {pb4.x, pb4.y, pb4.z, pb4.w};
#pragma unroll
            for (int i = 0; i < 4; i++)
#pragma unroll
                for (int j = 0; j < 4; j++) {
                    float d   = av[i] - pv[j];
                    float dab = fmaxf(d, 0.f);
                    float dba = dab - d;
                    float t = acc[i][j];
                    t = fmaf(apv[i], tpv[j], t);
                    t = fmaf(amv[i], dab, t);
                    t = fmaf(pbv[j], dba, t);
                    acc[i][j] = t;
                }
        }
        __syncthreads();
    }
#pragma unroll
    for (int i = 0; i < 4; i++)
#pragma unroll
        for (int j = 0; j < 4; j++)
            out[(size_t)(bn + ty * 4 + i) * ldo + bo + tx * 4 + j] = acc[i][j];
}

__global__ __launch_bounds__(256) void tversky_qkv(
    const float* __restrict__ feat, const float* __restrict__ tab,
    float* __restrict__ qkv)
{
    int z = blockIdx.z;
    const float* pf = feat + (size_t)(N_TOK + z * Dm) * Kf;
    const float* t3 = tab + z * 3;
    float* out = qkv + (size_t)z * N_TOK * Dm;
    tversky_tile(feat, pf, t3[0], t3[1], t3[2],
                 blockIdx.y * 64, blockIdx.x * 64, out, Dm);
}

// ---------------- Tversky 32x64 tile (for output projection; 256 blocks) ----
__global__ __launch_bounds__(256) void tversky_out(
    const float* __restrict__ cf, const float* __restrict__ feat,
    const float* __restrict__ tab, float* __restrict__ out)
{
    __shared__ float sxa[16][36], sxp[16][36], sxm[16][36];
    __shared__ float spa[16][68], spt[16][68], spb[16][68];
    const float* pf = feat + (size_t)(N_TOK + 3 * Dm) * Kf;
    const float th = tab[9], al = tab[10], be = tab[11];
    int tx = threadIdx.x, ty = threadIdx.y;
    int tid = ty * 16 + tx;
    int bn = blockIdx.y * 32, bo = blockIdx.x * 64;
    float acc[2][4] = {};
    for (int k0 = 0; k0 < Kf; k0 += 16) {
        {   // x planes: 16k x 32 rows = 512 slots
#pragma unroll
            for (int l = 0; l < 2; l++) {
                int e = tid + l * 256;
                int i = e >> 4, j = e & 15;
                float a = cf[(size_t)(bn + i) * Kf + k0 + j];
                sxa[j][i] = a;
                sxp[j][i] = fmaxf(a, 0.f);
                sxm[j][i] = (a > 0.f) ? -al : 0.f;
            }
        }
        {   // p planes: 16k x 64 rows = 1024 slots
#pragma unroll
            for (int l = 0; l < 4; l++) {
                int e = tid + l * 256;
                int i = e >> 4, j = e & 15;
                float p = pf[(size_t)(bo + i) * Kf + k0 + j];
                spa[j][i] = p;
                spt[j][i] = th * fmaxf(p, 0.f);
                spb[j][i] = (p > 0.f) ? -be : 0.f;
            }
        }
        __syncthreads();
#pragma unroll
        for (int k = 0; k < 16; k++) {
            float2 a2  = *(const float2*)&sxa[k][ty * 2];
            float2 ap2 = *(const float2*)&sxp[k][ty * 2];
            float2 am2 = *(const float2*)&sxm[k][ty * 2];
            float4 p4  = *(const float4*)&spa[k][tx * 4];
            float4 tp4 = *(const float4*)&spt[k][tx * 4];
            float4 pb4 = *(const float4*)&spb[k][tx * 4];
            float av[2]  = {a2.x, a2.y};
            float apv[2] = {ap2.x, ap2.y};
            float amv[2] = {am2.x, am2.y};
            float pv[4]  = {p4.x, p4.y, p4.z, p4.w};
            float tpv[4] = {tp4.x, tp4.y, tp4.z, tp4.w};
            float pbv[4] = {pb4.x, pb4.y, pb4.z, pb4.w};
#pragma unroll
            for (int i = 0; i < 2; i++)
#pragma unroll
                for (int j = 0; j < 4; j++) {
                    float d   = av[i] - pv[j];
                    float dab = fmaxf(d, 0.f);
                    float dba = dab - d;
                    float t = acc[i][j];
                    t = fmaf(apv[i], tpv[j], t);
                    t = fmaf(amv[i], dab, t);
                    t = fmaf(pbv[j], dba, t);
                    acc[i][j] = t;
                }
        }
        __syncthreads();
    }
#pragma unroll
    for (int i = 0; i < 2; i++)
#pragma unroll
        for (int j = 0; j < 4; j++)
            out[(size_t)(bn + ty * 2 + i) * Dm + bo + tx * 4 + j] = acc[i][j];
}

// ---------------- fully fused attention: scores+mask+softmax+ctx ------------
// Block 256 (16x16), q-tile 32, per-(b,h). Grid (16 q-tiles, 16 z).
// probs live in registers acc[2][32]; ctx computed via smem-staged chunks.
__global__ __launch_bounds__(256) void attn_fused(
    const float* __restrict__ Q, const float* __restrict__ Km,
    const float* __restrict__ V, const int* __restrict__ mask,
    float* __restrict__ ctx)
{
    __shared__ float Qs[64][36];   // [d][q]
    __shared__ float Ks[64][68];   // [d][k]  (reused as Vs[k][d])
    __shared__ float Ps[32][68];   // [q][k-chunk]
    int z = blockIdx.y;
    int b = z >> 3, h = z & 7;
    const float* Qg = Q  + (size_t)b * Sq * Dm + h * DK;
    const float* Kg = Km + (size_t)b * Sq * Dm + h * DK;
    const float* Vg = V  + (size_t)b * Sq * Dm + h * DK;
    int bq = blockIdx.x * 32;
    int tx = threadIdx.x, ty = threadIdx.y;
    int tid = ty * 16 + tx;

#pragma unroll
    for (int l = 0; l < 8; l++) {          // Qs: 32q x 64d
        int e = tid + l * 256;
        int m = e >> 6, d = e & 63;
        Qs[d][m] = Qg[(size_t)(bq + m) * Dm + d];
    }

    float acc[2][32];
#pragma unroll
    for (int s = 0; s < 2; s++)
#pragma unroll
        for (int c = 0; c < 32; c++) acc[s][c] = 0.f;

    for (int kc = 0; kc < 8; kc++) {
        int bk = kc * 64;
#pragma unroll
        for (int l = 0; l < 16; l++) {     // Ks[d][k]
            int e = tid + l * 256;
            int kk = e >> 6, d = e & 63;
            Ks[d][kk] = Kg[(size_t)(bk + kk) * Dm + d];
        }
        __syncthreads();
#pragma unroll
        for (int d = 0; d < 64; d++) {
            float a0 = Qs[d][ty * 2];
            float a1 = Qs[d][ty * 2 + 1];
            float4 b4 = *(const float4*)&Ks[d][tx * 4];
            acc[0][kc*4+0] = fmaf(a0, b4.x, acc[0][kc*4+0]);
            acc[0][kc*4+1] = fmaf(a0, b4.y, acc[0][kc*4+1]);
            acc[0][kc*4+2] = fmaf(a0, b4.z, acc[0][kc*4+2]);
            acc[0][kc*4+3] = fmaf(a0, b4.w, acc[0][kc*4+3]);
            acc[1][kc*4+0] = fmaf(a1, b4.x, acc[1][kc*4+0]);
            acc[1][kc*4+1] = fmaf(a1, b4.y, acc[1][kc*4+1]);
            acc[1][kc*4+2] = fmaf(a1, b4.z, acc[1][kc*4+2]);
            acc[1][kc*4+3] = fmaf(a1, b4.w, acc[1][kc*4+3]);
        }
        __syncthreads();
    }

    // mask
    const int* mg = mask + (size_t)b * Sq * Sq;
#pragma unroll
    for (int s = 0; s < 2; s++) {
        int row = bq + ty * 2 + s;
#pragma unroll
        for (int kc = 0; kc < 8; kc++) {
            int4 m4 = *(const int4*)&mg[(size_t)row * Sq + kc * 64 + tx * 4];
            if (m4.x == 0) acc[s][kc*4+0] = -INFINITY;
            if (m4.y == 0) acc[s][kc*4+1] = -INFINITY;
            if (m4.z == 0) acc[s][kc*4+2] = -INFINITY;
            if (m4.w == 0) acc[s][kc*4+3] = -INFINITY;
        }
    }

    // softmax over 512 (16 tx lanes hold a row; shfl within warp half)
    float m0 = -INFINITY, m1 = -INFINITY;
#pragma unroll
    for (int c = 0; c < 32; c++) {
        m0 = fmaxf(m0, acc[0][c]);
        m1 = fmaxf(m1, acc[1][c]);
    }
#pragma unroll
    for (int o = 8; o; o >>= 1) {
        m0 = fmaxf(m0, __shfl_xor_sync(0xffffffffu, m0, o));
        m1 = fmaxf(m1, __shfl_xor_sync(0xffffffffu, m1, o));
    }
    float s0 = 0.f, s1 = 0.f;
#pragma unroll
    for (int c = 0; c < 32; c++) {
        float e0 = __expf((acc[0][c] - m0) * 0.125f);
        float e1 = __expf((acc[1][c] - m1) * 0.125f);
        acc[0][c] = e0; s0 += e0;
        acc[1][c] = e1; s1 += e1;
    }
#pragma unroll
    for (int o = 8; o; o >>= 1) {
        s0 += __shfl_xor_sync(0xffffffffu, s0, o);
        s1 += __shfl_xor_sync(0xffffffffu, s1, o);
    }
    float i0 = 1.f / s0, i1 = 1.f / s1;
#pragma unroll
    for (int c = 0; c < 32; c++) { acc[0][c] *= i0; acc[1][c] *= i1; }

    // ctx = probs @ V, staged per 64-k chunk (reuse Ks as Vs[k][d])
    float cacc[2][4] = {};
    for (int kc = 0; kc < 8; kc++) {
        *(float4*)&Ps[ty * 2][tx * 4] =
            make_float4(acc[0][kc*4+0], acc[0][kc*4+1], acc[0][kc*4+2], acc[0][kc*4+3]);
        *(float4*)&Ps[ty * 2 + 1][tx * 4] =
            make_float4(acc[1][kc*4+0], acc[1][kc*4+1], acc[1][kc*4+2], acc[1][kc*4+3]);
#pragma unroll
        for (int l = 0; l < 16; l++) {     // Vs[k][d] into Ks array
            int e = tid + l * 256;
            int kk = e >> 6, d = e & 63;
            Ks[kk][d] = Vg[(size_t)(kc * 64 + kk) * Dm + d];
        }
        __syncthreads();
#pragma unroll
        for (int k = 0; k < 64; k++) {
            float a0 = Ps[ty * 2][k];
            float a1 = Ps[ty * 2 + 1][k];
            float4 b4 = *(const float4*)&Ks[k][tx * 4];
            cacc[0][0] = fmaf(a0, b4.x, cacc[0][0]);
            cacc[0][1] = fmaf(a0, b4.y, cacc[0][1]);
            cacc[0][2] = fmaf(a0, b4.z, cacc[0][2]);
            cacc[0][3] = fmaf(a0, b4.w, cacc[0][3]);
            cacc[1][0] = fmaf(a1, b4.x, cacc[1][0]);
            cacc[1][1] = fmaf(a1, b4.y, cacc[1][1]);
            cacc[1][2] = fmaf(a1, b4.z, cacc[1][2]);
            cacc[1][3] = fmaf(a1, b4.w, cacc[1][3]);
        }
        __syncthreads();
    }

    float* cg = ctx + (size_t)b * Sq * Dm + h * DK;
    *(float4*)&cg[(size_t)(bq + ty * 2)     * Dm + tx * 4] =
        make_float4(cacc[0][0], cacc[0][1], cacc[0][2], cacc[0][3]);
    *(float4*)&cg[(size_t)(bq + ty * 2 + 1) * Dm + tx * 4] =
        make_float4(cacc[1][0], cacc[1][1], cacc[1][2], cacc[1][3]);
}

// ---------------- launch ----------------------------------------------------
extern "C" void kernel_launch(void* const* d_in, const int* in_sizes, int n_in,
                              void* d_out, int out_size)
{
    const float* x     = (const float*)d_in[0];
    const int*   mask  = (const int*)d_in[1];
    const float* omega = (const float*)d_in[2];
    const float* Pq    = (const float*)d_in[3];
    const float* Pk    = (const float*)d_in[4];
    const float* Pv    = (const float*)d_in[5];
    const float* Po    = (const float*)d_in[6];
    const float* tab   = (const float*)d_in[7];
    float* out = (float*)d_out;

    float *p_feat, *p_qkv, *p_ctx, *p_cfp, *p_cf;
    cudaGetSymbolAddress((void**)&p_feat, g_feat);
    cudaGetSymbolAddress((void**)&p_qkv, g_QKV);
    cudaGetSymbolAddress((void**)&p_ctx, g_ctx);
    cudaGetSymbolAddress((void**)&p_cfp, g_cfp);
    cudaGetSymbolAddress((void**)&p_cf, g_cf);

    float* p_Q = p_qkv;
    float* p_K = p_qkv + (size_t)N_TOK * Dm;
    float* p_V = p_qkv + (size_t)2 * N_TOK * Dm;

    dim3 blk(16, 16);

    // feature maps
    feat_gemm<<<dim3(2, 48), blk>>>(x, Pq, Pk, Pv, Po, omega, p_feat);

    // Q, K, V projections
    tversky_qkv<<<dim3(8, 16, 3), blk>>>(p_feat, tab, p_qkv);

    // fused attention
    attn_fused<<<dim3(16, 16), blk>>>(p_Q, p_K, p_V, mask, p_ctx);

    // output projection: split-K GEMM + add, then Tversky (32x64 tiles)
    gemm_split<<<dim3(2, 16, 4), blk>>>(p_ctx, omega, p_cfp);
    add4<<<(N_TOK * Kf / 4) / 256, 256>>>(p_cfp, p_cf);
    tversky_out<<<dim3(8, 32), blk>>>(p_cf, p_feat, tab, out);
}

// round 8
// speedup vs baseline: 1.2850x; 1.1019x over previous
#include <cuda_runtime.h>
#include <math.h>

#define N_TOK 1024
#define Dm 512
#define Kf 128
#define Sq 512
#define DK 64

// ---------------- scratch ---------------------------------------------------
__device__ float g_feat[(N_TOK + 4 * Dm) * Kf];
__device__ float g_R[N_TOK + 4 * Dm];      // row relu-sums of feat
__device__ float g_Rcf[N_TOK];             // row relu-sums of cf
__device__ float g_QKV[3 * N_TOK * Dm];
__device__ float g_ctx[N_TOK * Dm];
__device__ float g_cfp[8][N_TOK * Kf];     // split-K partials
__device__ float g_cf[N_TOK * Kf];

// ---------------- feature GEMM: feat = [x;Pq;Pk;Pv;Po] @ omega --------------
// M-tile 32, N-tile 64, grid (2, 96) = 192 blocks.
__global__ __launch_bounds__(256) void feat_gemm(
    const float* __restrict__ x,  const float* __restrict__ Pq,
    const float* __restrict__ Pk, const float* __restrict__ Pv,
    const float* __restrict__ Po, const float* __restrict__ omega,
    float* __restrict__ feat)
{
    __shared__ float As[32][36];
    __shared__ float Bs[32][68];
    int tx = threadIdx.x, ty = threadIdx.y;
    int tid = ty * 16 + tx;
    int bm = blockIdx.y * 32, bn = blockIdx.x * 64;

    const float* A;
    int row0;
    if (bm < N_TOK) { A = x; row0 = bm; }
    else {
        int s = (bm - N_TOK) >> 9;
        const float* Ps[4] = {Pq, Pk, Pv, Po};
        A = Ps[s]; row0 = (bm - N_TOK) & 511;
    }

    float acc[2][4] = {};
    for (int k0 = 0; k0 < Dm; k0 += 32) {
#pragma unroll
        for (int l = 0; l < 4; l++) {          // A: 32m x 32k
            int e = tid + l * 256;
            int i = e >> 5, j = e & 31;
            As[j][i] = A[(size_t)(row0 + i) * Dm + k0 + j];
        }
#pragma unroll
        for (int l = 0; l < 8; l++) {          // B: 32k x 64n
            int e = tid + l * 256;
            int kk = e >> 6, j = e & 63;
            Bs[kk][j] = omega[(size_t)(k0 + kk) * Kf + bn + j];
        }
        __syncthreads();
#pragma unroll
        for (int k = 0; k < 32; k++) {
            float2 a2 = *(const float2*)&As[k][ty * 2];
            float4 b4 = *(const float4*)&Bs[k][tx * 4];
            acc[0][0] = fmaf(a2.x, b4.x, acc[0][0]);
            acc[0][1] = fmaf(a2.x, b4.y, acc[0][1]);
            acc[0][2] = fmaf(a2.x, b4.z, acc[0][2]);
            acc[0][3] = fmaf(a2.x, b4.w, acc[0][3]);
            acc[1][0] = fmaf(a2.y, b4.x, acc[1][0]);
            acc[1][1] = fmaf(a2.y, b4.y, acc[1][1]);
            acc[1][2] = fmaf(a2.y, b4.z, acc[1][2]);
            acc[1][3] = fmaf(a2.y, b4.w, acc[1][3]);
        }
        __syncthreads();
    }
#pragma unroll
    for (int i = 0; i < 2; i++)
#pragma unroll
        for (int j = 0; j < 4; j++)
            feat[(size_t)(bm + ty * 2 + i) * Kf + bn + tx * 4 + j] = acc[i][j];
}

// ---------------- split-K GEMM (K split 8): cfp[z] = ctx @ omega chunk ------
__global__ __launch_bounds__(256) void gemm_split(
    const float* __restrict__ A, const float* __restrict__ B,
    float* __restrict__ Cp)
{
    __shared__ float As[32][68];
    __shared__ float Bs[32][68];
    int tx = threadIdx.x, ty = threadIdx.y;
    int tid = ty * 16 + tx;
    int bm = blockIdx.y * 64, bn = blockIdx.x * 64;
    int kbase = blockIdx.z * 64;
    float* C = Cp + (size_t)blockIdx.z * N_TOK * Kf;
    float acc[4][4] = {};
    for (int k0 = kbase; k0 < kbase + 64; k0 += 32) {
#pragma unroll
        for (int l = 0; l < 8; l++) {
            int e = tid + l * 256;
            int i = e >> 5, j = e & 31;
            As[j][i] = A[(size_t)(bm + i) * Dm + k0 + j];
        }
#pragma unroll
        for (int l = 0; l < 8; l++) {
            int e = tid + l * 256;
            int kk = e >> 6, j = e & 63;
            Bs[kk][j] = B[(size_t)(k0 + kk) * Kf + bn + j];
        }
        __syncthreads();
#pragma unroll
        for (int k = 0; k < 32; k++) {
            float4 a4 = *(const float4*)&As[k][ty * 4];
            float4 b4 = *(const float4*)&Bs[k][tx * 4];
            float av[4] = {a4.x, a4.y, a4.z, a4.w};
            float bv[4] = {b4.x, b4.y, b4.z, b4.w};
#pragma unroll
            for (int i = 0; i < 4; i++)
#pragma unroll
                for (int j = 0; j < 4; j++)
                    acc[i][j] = fmaf(av[i], bv[j], acc[i][j]);
        }
        __syncthreads();
    }
#pragma unroll
    for (int i = 0; i < 4; i++)
#pragma unroll
        for (int j = 0; j < 4; j++)
            C[(size_t)(bm + ty * 4 + i) * Kf + bn + tx * 4 + j] = acc[i][j];
}

__global__ __launch_bounds__(256) void add8(const float* __restrict__ Cp,
                                            float* __restrict__ C)
{
    int idx = blockIdx.x * 256 + threadIdx.x;      // float4 index
    const size_t n = (size_t)N_TOK * Kf;
    float4 r = ((const float4*)Cp)[idx];
#pragma unroll
    for (int z = 1; z < 8; z++) {
        float4 a = ((const float4*)(Cp + (size_t)z * n))[idx];
        r.x += a.x; r.y += a.y; r.z += a.z; r.w += a.w;
    }
    ((float4*)C)[idx] = r;
}

// ---------------- row relu-sums ---------------------------------------------
__global__ __launch_bounds__(256) void rowrelu(const float* __restrict__ f,
                                               float* __restrict__ R)
{
    int row = blockIdx.x * 8 + threadIdx.y;
    int lane = threadIdx.x;
    float4 v = ((const float4*)(f + (size_t)row * Kf))[lane];
    float s = fmaxf(v.x, 0.f) + fmaxf(v.y, 0.f) + fmaxf(v.z, 0.f) + fmaxf(v.w, 0.f);
#pragma unroll
    for (int o = 16; o; o >>= 1) s += __shfl_xor_sync(0xffffffffu, s, o);
    if (lane == 0) R[row] = s;
}

// ---------------- Tversky 64x64 tile, min-trick (3 fma-pipe ops/pair-k) -----
// sim_k = th*ar*pr + (al*xm + be*pm)*min(a,p)      (accumulated)
// out   = acc - al*Rx[i] - be*Rp[j]
// with ar=relu(a), pr=relu(p), xm=[a>0], pm=[p>0].
__device__ __forceinline__ void tversky_tile(
    const float* __restrict__ xf, const float* __restrict__ pf,
    const float* __restrict__ Rx, const float* __restrict__ Rp,
    float th, float al, float be, int bn, int bo,
    float* __restrict__ out, int ldo)
{
    __shared__ float sxa[16][68], sxA[16][68], sxW[16][68];
    __shared__ float spa[16][68], spP[16][68], spW[16][68];
    int tx = threadIdx.x, ty = threadIdx.y;
    int tid = ty * 16 + tx;
    float acc[4][4] = {};
    for (int k0 = 0; k0 < Kf; k0 += 16) {
#pragma unroll
        for (int l = 0; l < 4; l++) {
            int e = tid + l * 256;
            int i = e >> 4, j = e & 15;
            float a = xf[(size_t)(bn + i) * Kf + k0 + j];
            sxa[j][i] = a;
            sxA[j][i] = th * fmaxf(a, 0.f);
            sxW[j][i] = (a > 0.f) ? al : 0.f;
            float p = pf[(size_t)(bo + i) * Kf + k0 + j];
            spa[j][i] = p;
            spP[j][i] = fmaxf(p, 0.f);
            spW[j][i] = (p > 0.f) ? be : 0.f;
        }
        __syncthreads();
#pragma unroll
        for (int k = 0; k < 16; k++) {
            float4 a4 = *(const float4*)&sxa[k][ty * 4];
            float4 A4 = *(const float4*)&sxA[k][ty * 4];
            float4 w4 = *(const float4*)&sxW[k][ty * 4];
            float4 p4 = *(const float4*)&spa[k][tx * 4];
            float4 P4 = *(const float4*)&spP[k][tx * 4];
            float4 v4 = *(const float4*)&spW[k][tx * 4];
            float av[4] = {a4.x, a4.y, a4.z, a4.w};
            float Av[4] = {A4.x, A4.y, A4.z, A4.w};
            float wv[4] = {w4.x, w4.y, w4.z, w4.w};
            float pv[4] = {p4.x, p4.y, p4.z, p4.w};
            float Pv[4] = {P4.x, P4.y, P4.z, P4.w};
            float vv[4] = {v4.x, v4.y, v4.z, v4.w};
#pragma unroll
            for (int i = 0; i < 4; i++)
#pragma unroll
                for (int j = 0; j < 4; j++) {
                    float m = fminf(av[i], pv[j]);
                    float t = acc[i][j];
                    t = fmaf(Av[i], Pv[j], t);
                    t = fmaf(wv[i], m, t);
                    t = fmaf(vv[j], m, t);
                    acc[i][j] = t;
                }
        }
        __syncthreads();
    }
    float rx[4], rp[4];
#pragma unroll
    for (int i = 0; i < 4; i++) rx[i] = al * Rx[bn + ty * 4 + i];
#pragma unroll
    for (int j = 0; j < 4; j++) rp[j] = be * Rp[bo + tx * 4 + j];
#pragma unroll
    for (int i = 0; i < 4; i++)
#pragma unroll
        for (int j = 0; j < 4; j++)
            out[(size_t)(bn + ty * 4 + i) * ldo + bo + tx * 4 + j] =
                acc[i][j] - rx[i] - rp[j];
}

__global__ __launch_bounds__(256) void tversky_qkv(
    const float* __restrict__ feat, const float* __restrict__ R,
    const float* __restrict__ tab, float* __restrict__ qkv)
{
    int z = blockIdx.z;
    const float* pf = feat + (size_t)(N_TOK + z * Dm) * Kf;
    const float* Rp = R + N_TOK + z * Dm;
    const float* t3 = tab + z * 3;
    float* out = qkv + (size_t)z * N_TOK * Dm;
    tversky_tile(feat, pf, R, Rp, t3[0], t3[1], t3[2],
                 blockIdx.y * 64, blockIdx.x * 64, out, Dm);
}

__global__ __launch_bounds__(256) void tversky_out(
    const float* __restrict__ cf, const float* __restrict__ Rcf,
    const float* __restrict__ feat, const float* __restrict__ R,
    const float* __restrict__ tab, float* __restrict__ out)
{
    const float* pf = feat + (size_t)(N_TOK + 3 * Dm) * Kf;
    const float* Rp = R + N_TOK + 3 * Dm;
    tversky_tile(cf, pf, Rcf, Rp, tab[9], tab[10], tab[11],
                 blockIdx.y * 64, blockIdx.x * 64, out, Dm);
}

// ---------------- fully fused attention: scores+mask+softmax+ctx ------------
__global__ __launch_bounds__(256) void attn_fused(
    const float* __restrict__ Q, const float* __restrict__ Km,
    const float* __restrict__ V, const int* __restrict__ mask,
    float* __restrict__ ctx)
{
    __shared__ float Qs[64][36];   // [d][q]
    __shared__ float Ks[64][68];   // [d][k]  (reused as Vs[k][d])
    __shared__ float Ps[32][68];   // [q][k-chunk]
    int z = blockIdx.y;
    int b = z >> 3, h = z & 7;
    const float* Qg = Q  + (size_t)b * Sq * Dm + h * DK;
    const float* Kg = Km + (size_t)b * Sq * Dm + h * DK;
    const float* Vg = V  + (size_t)b * Sq * Dm + h * DK;
    int bq = blockIdx.x * 32;
    int tx = threadIdx.x, ty = threadIdx.y;
    int tid = ty * 16 + tx;

#pragma unroll
    for (int l = 0; l < 8; l++) {
        int e = tid + l * 256;
        int m = e >> 6, d = e & 63;
        Qs[d][m] = Qg[(size_t)(bq + m) * Dm + d];
    }

    float acc[2][32];
#pragma unroll
    for (int s = 0; s < 2; s++)
#pragma unroll
        for (int c = 0; c < 32; c++) acc[s][c] = 0.f;

    for (int kc = 0; kc < 8; kc++) {
        int bk = kc * 64;
#pragma unroll
        for (int l = 0; l < 16; l++) {
            int e = tid + l * 256;
            int kk = e >> 6, d = e & 63;
            Ks[d][kk] = Kg[(size_t)(bk + kk) * Dm + d];
        }
        __syncthreads();
#pragma unroll
        for (int d = 0; d < 64; d++) {
            float a0 = Qs[d][ty * 2];
            float a1 = Qs[d][ty * 2 + 1];
            float4 b4 = *(const float4*)&Ks[d][tx * 4];
            acc[0][kc*4+0] = fmaf(a0, b4.x, acc[0][kc*4+0]);
            acc[0][kc*4+1] = fmaf(a0, b4.y, acc[0][kc*4+1]);
            acc[0][kc*4+2] = fmaf(a0, b4.z, acc[0][kc*4+2]);
            acc[0][kc*4+3] = fmaf(a0, b4.w, acc[0][kc*4+3]);
            acc[1][kc*4+0] = fmaf(a1, b4.x, acc[1][kc*4+0]);
            acc[1][kc*4+1] = fmaf(a1, b4.y, acc[1][kc*4+1]);
            acc[1][kc*4+2] = fmaf(a1, b4.z, acc[1][kc*4+2]);
            acc[1][kc*4+3] = fmaf(a1, b4.w, acc[1][kc*4+3]);
        }
        __syncthreads();
    }

    const int* mg = mask + (size_t)b * Sq * Sq;
#pragma unroll
    for (int s = 0; s < 2; s++) {
        int row = bq + ty * 2 + s;
#pragma unroll
        for (int kc = 0; kc < 8; kc++) {
            int4 m4 = *(const int4*)&mg[(size_t)row * Sq + kc * 64 + tx * 4];
            if (m4.x == 0) acc[s][kc*4+0] = -INFINITY;
            if (m4.y == 0) acc[s][kc*4+1] = -INFINITY;
            if (m4.z == 0) acc[s][kc*4+2] = -INFINITY;
            if (m4.w == 0) acc[s][kc*4+3] = -INFINITY;
        }
    }

    float m0 = -INFINITY, m1 = -INFINITY;
#pragma unroll
    for (int c = 0; c < 32; c++) {
        m0 = fmaxf(m0, acc[0][c]);
        m1 = fmaxf(m1, acc[1][c]);
    }
#pragma unroll
    for (int o = 8; o; o >>= 1) {
        m0 = fmaxf(m0, __shfl_xor_sync(0xffffffffu, m0, o));
        m1 = fmaxf(m1, __shfl_xor_sync(0xffffffffu, m1, o));
    }
    float s0 = 0.f, s1 = 0.f;
#pragma unroll
    for (int c = 0; c < 32; c++) {
        float e0 = __expf((acc[0][c] - m0) * 0.125f);
        float e1 = __expf((acc[1][c] - m1) * 0.125f);
        acc[0][c] = e0; s0 += e0;
        acc[1][c] = e1; s1 += e1;
    }
#pragma unroll
    for (int o = 8; o; o >>= 1) {
        s0 += __shfl_xor_sync(0xffffffffu, s0, o);
        s1 += __shfl_xor_sync(0xffffffffu, s1, o);
    }
    float i0 = 1.f / s0, i1 = 1.f / s1;
#pragma unroll
    for (int c = 0; c < 32; c++) { acc[0][c] *= i0; acc[1][c] *= i1; }

    float cacc[2][4] = {};
    for (int kc = 0; kc < 8; kc++) {
        *(float4*)&Ps[ty * 2][tx * 4] =
            make_float4(acc[0][kc*4+0], acc[0][kc*4+1], acc[0][kc*4+2], acc[0][kc*4+3]);
        *(float4*)&Ps[ty * 2 + 1][tx * 4] =
            make_float4(acc[1][kc*4+0], acc[1][kc*4+1], acc[1][kc*4+2], acc[1][kc*4+3]);
#pragma unroll
        for (int l = 0; l < 16; l++) {
            int e = tid + l * 256;
            int kk = e >> 6, d = e & 63;
            Ks[kk][d] = Vg[(size_t)(kc * 64 + kk) * Dm + d];
        }
        __syncthreads();
#pragma unroll
        for (int k = 0; k < 64; k++) {
            float a0 = Ps[ty * 2][k];
            float a1 = Ps[ty * 2 + 1][k];
            float4 b4 = *(const float4*)&Ks[k][tx * 4];
            cacc[0][0] = fmaf(a0, b4.x, cacc[0][0]);
            cacc[0][1] = fmaf(a0, b4.y, cacc[0][1]);
            cacc[0][2] = fmaf(a0, b4.z, cacc[0][2]);
            cacc[0][3] = fmaf(a0, b4.w, cacc[0][3]);
            cacc[1][0] = fmaf(a1, b4.x, cacc[1][0]);
            cacc[1][1] = fmaf(a1, b4.y, cacc[1][1]);
            cacc[1][2] = fmaf(a1, b4.z, cacc[1][2]);
            cacc[1][3] = fmaf(a1, b4.w, cacc[1][3]);
        }
        __syncthreads();
    }

    float* cg = ctx + (size_t)b * Sq * Dm + h * DK;
    *(float4*)&cg[(size_t)(bq + ty * 2)     * Dm + tx * 4] =
        make_float4(cacc[0][0], cacc[0][1], cacc[0][2], cacc[0][3]);
    *(float4*)&cg[(size_t)(bq + ty * 2 + 1) * Dm + tx * 4] =
        make_float4(cacc[1][0], cacc[1][1], cacc[1][2], cacc[1][3]);
}

// ---------------- launch ----------------------------------------------------
extern "C" void kernel_launch(void* const* d_in, const int* in_sizes, int n_in,
                              void* d_out, int out_size)
{
    const float* x     = (const float*)d_in[0];
    const int*   mask  = (const int*)d_in[1];
    const float* omega = (const float*)d_in[2];
    const float* Pq    = (const float*)d_in[3];
    const float* Pk    = (const float*)d_in[4];
    const float* Pv    = (const float*)d_in[5];
    const float* Po    = (const float*)d_in[6];
    const float* tab   = (const float*)d_in[7];
    float* out = (float*)d_out;

    float *p_feat, *p_R, *p_Rcf, *p_qkv, *p_ctx, *p_cfp, *p_cf;
    cudaGetSymbolAddress((void**)&p_feat, g_feat);
    cudaGetSymbolAddress((void**)&p_R, g_R);
    cudaGetSymbolAddress((void**)&p_Rcf, g_Rcf);
    cudaGetSymbolAddress((void**)&p_qkv, g_QKV);
    cudaGetSymbolAddress((void**)&p_ctx, g_ctx);
    cudaGetSymbolAddress((void**)&p_cfp, g_cfp);
    cudaGetSymbolAddress((void**)&p_cf, g_cf);

    float* p_Q = p_qkv;
    float* p_K = p_qkv + (size_t)N_TOK * Dm;
    float* p_V = p_qkv + (size_t)2 * N_TOK * Dm;

    dim3 blk(16, 16);

    // feature maps + row relu-sums
    feat_gemm<<<dim3(2, 96), blk>>>(x, Pq, Pk, Pv, Po, omega, p_feat);
    rowrelu<<<(N_TOK + 4 * Dm) / 8, dim3(32, 8)>>>(p_feat, p_R);

    // Q, K, V projections (min-trick)
    tversky_qkv<<<dim3(8, 16, 3), blk>>>(p_feat, p_R, tab, p_qkv);

    // fused attention
    attn_fused<<<dim3(16, 16), blk>>>(p_Q, p_K, p_V, mask, p_ctx);

    // output projection: split-K(8) GEMM + add, rowrelu, tversky (min-trick)
    gemm_split<<<dim3(2, 16, 8), blk>>>(p_ctx, omega, p_cfp);
    add8<<<(N_TOK * Kf / 4) / 256, 256>>>(p_cfp, p_cf);
    rowrelu<<<N_TOK / 8, dim3(32, 8)>>>(p_cf, p_Rcf);
    tversky_out<<<dim3(8, 16), blk>>>(p_cf, p_Rcf, p_feat, p_R, tab, out);
}

// round 9
// speedup vs baseline: 1.3157x; 1.0239x over previous
#include <cuda_runtime.h>
#include <math.h>

#define N_TOK 1024
#define Dm 512
#define Kf 128
#define Sq 512
#define DK 64

// ---------------- scratch ---------------------------------------------------
__device__ float g_feat[(N_TOK + 4 * Dm) * Kf];
__device__ float g_R[N_TOK + 4 * Dm];      // row relu-sums of feat
__device__ float g_Rcf[N_TOK];             // row relu-sums of cf
__device__ float g_QKV[3 * N_TOK * Dm];
__device__ float g_ctx[N_TOK * Dm];
__device__ float g_cfp[8][N_TOK * Kf];     // split-K partials
__device__ float g_cf[N_TOK * Kf];

// ---------------- feature GEMM: feat = [x;Pq;Pk;Pv;Po] @ omega --------------
__global__ __launch_bounds__(256) void feat_gemm(
    const float* __restrict__ x,  const float* __restrict__ Pq,
    const float* __restrict__ Pk, const float* __restrict__ Pv,
    const float* __restrict__ Po, const float* __restrict__ omega,
    float* __restrict__ feat)
{
    __shared__ float As[32][36];
    __shared__ float Bs[32][68];
    int tx = threadIdx.x, ty = threadIdx.y;
    int tid = ty * 16 + tx;
    int bm = blockIdx.y * 32, bn = blockIdx.x * 64;

    const float* A;
    int row0;
    if (bm < N_TOK) { A = x; row0 = bm; }
    else {
        int s = (bm - N_TOK) >> 9;
        const float* Ps[4] = {Pq, Pk, Pv, Po};
        A = Ps[s]; row0 = (bm - N_TOK) & 511;
    }

    float acc[2][4] = {};
    for (int k0 = 0; k0 < Dm; k0 += 32) {
#pragma unroll
        for (int l = 0; l < 4; l++) {
            int e = tid + l * 256;
            int i = e >> 5, j = e & 31;
            As[j][i] = A[(size_t)(row0 + i) * Dm + k0 + j];
        }
#pragma unroll
        for (int l = 0; l < 8; l++) {
            int e = tid + l * 256;
            int kk = e >> 6, j = e & 63;
            Bs[kk][j] = omega[(size_t)(k0 + kk) * Kf + bn + j];
        }
        __syncthreads();
#pragma unroll
        for (int k = 0; k < 32; k++) {
            float2 a2 = *(const float2*)&As[k][ty * 2];
            float4 b4 = *(const float4*)&Bs[k][tx * 4];
            acc[0][0] = fmaf(a2.x, b4.x, acc[0][0]);
            acc[0][1] = fmaf(a2.x, b4.y, acc[0][1]);
            acc[0][2] = fmaf(a2.x, b4.z, acc[0][2]);
            acc[0][3] = fmaf(a2.x, b4.w, acc[0][3]);
            acc[1][0] = fmaf(a2.y, b4.x, acc[1][0]);
            acc[1][1] = fmaf(a2.y, b4.y, acc[1][1]);
            acc[1][2] = fmaf(a2.y, b4.z, acc[1][2]);
            acc[1][3] = fmaf(a2.y, b4.w, acc[1][3]);
        }
        __syncthreads();
    }
#pragma unroll
    for (int i = 0; i < 2; i++)
#pragma unroll
        for (int j = 0; j < 4; j++)
            feat[(size_t)(bm + ty * 2 + i) * Kf + bn + tx * 4 + j] = acc[i][j];
}

// ---------------- split-K GEMM (K split 8) ----------------------------------
__global__ __launch_bounds__(256) void gemm_split(
    const float* __restrict__ A, const float* __restrict__ B,
    float* __restrict__ Cp)
{
    __shared__ float As[32][68];
    __shared__ float Bs[32][68];
    int tx = threadIdx.x, ty = threadIdx.y;
    int tid = ty * 16 + tx;
    int bm = blockIdx.y * 64, bn = blockIdx.x * 64;
    int kbase = blockIdx.z * 64;
    float* C = Cp + (size_t)blockIdx.z * N_TOK * Kf;
    float acc[4][4] = {};
    for (int k0 = kbase; k0 < kbase + 64; k0 += 32) {
#pragma unroll
        for (int l = 0; l < 8; l++) {
            int e = tid + l * 256;
            int i = e >> 5, j = e & 31;
            As[j][i] = A[(size_t)(bm + i) * Dm + k0 + j];
        }
#pragma unroll
        for (int l = 0; l < 8; l++) {
            int e = tid + l * 256;
            int kk = e >> 6, j = e & 63;
            Bs[kk][j] = B[(size_t)(k0 + kk) * Kf + bn + j];
        }
        __syncthreads();
#pragma unroll
        for (int k = 0; k < 32; k++) {
            float4 a4 = *(const float4*)&As[k][ty * 4];
            float4 b4 = *(const float4*)&Bs[k][tx * 4];
            float av[4] = {a4.x, a4.y, a4.z, a4.w};
            float bv[4] = {b4.x, b4.y, b4.z, b4.w};
#pragma unroll
            for (int i = 0; i < 4; i++)
#pragma unroll
                for (int j = 0; j < 4; j++)
                    acc[i][j] = fmaf(av[i], bv[j], acc[i][j]);
        }
        __syncthreads();
    }
#pragma unroll
    for (int i = 0; i < 4; i++)
#pragma unroll
        for (int j = 0; j < 4; j++)
            C[(size_t)(bm + ty * 4 + i) * Kf + bn + tx * 4 + j] = acc[i][j];
}

__global__ __launch_bounds__(256) void add8(const float* __restrict__ Cp,
                                            float* __restrict__ C)
{
    int idx = blockIdx.x * 256 + threadIdx.x;
    const size_t n = (size_t)N_TOK * Kf;
    float4 r = ((const float4*)Cp)[idx];
#pragma unroll
    for (int z = 1; z < 8; z++) {
        float4 a = ((const float4*)(Cp + (size_t)z * n))[idx];
        r.x += a.x; r.y += a.y; r.z += a.z; r.w += a.w;
    }
    ((float4*)C)[idx] = r;
}

// ---------------- row relu-sums ---------------------------------------------
__global__ __launch_bounds__(256) void rowrelu(const float* __restrict__ f,
                                               float* __restrict__ R)
{
    int row = blockIdx.x * 8 + threadIdx.y;
    int lane = threadIdx.x;
    float4 v = ((const float4*)(f + (size_t)row * Kf))[lane];
    float s = fmaxf(v.x, 0.f) + fmaxf(v.y, 0.f) + fmaxf(v.z, 0.f) + fmaxf(v.w, 0.f);
#pragma unroll
    for (int o = 16; o; o >>= 1) s += __shfl_xor_sync(0xffffffffu, s, o);
    if (lane == 0) R[row] = s;
}

// ---------------- Tversky 64x64 tile, min-trick -----------------------------
// sim_k = th*ar*pr + (al*xm + be*pm)*min(a,p);  out = acc - al*Rx - be*Rp
__device__ __forceinline__ void tversky_tile(
    const float* __restrict__ xf, const float* __restrict__ pf,
    const float* __restrict__ Rx, const float* __restrict__ Rp,
    float th, float al, float be, int bn, int bo,
    float* __restrict__ out, int ldo)
{
    __shared__ float sxa[16][68], sxA[16][68], sxW[16][68];
    __shared__ float spa[16][68], spP[16][68], spW[16][68];
    int tx = threadIdx.x, ty = threadIdx.y;
    int tid = ty * 16 + tx;
    float acc[4][4] = {};
    for (int k0 = 0; k0 < Kf; k0 += 16) {
#pragma unroll
        for (int l = 0; l < 4; l++) {
            int e = tid + l * 256;
            int i = e >> 4, j = e & 15;
            float a = xf[(size_t)(bn + i) * Kf + k0 + j];
            sxa[j][i] = a;
            sxA[j][i] = th * fmaxf(a, 0.f);
            sxW[j][i] = (a > 0.f) ? al : 0.f;
            float p = pf[(size_t)(bo + i) * Kf + k0 + j];
            spa[j][i] = p;
            spP[j][i] = fmaxf(p, 0.f);
            spW[j][i] = (p > 0.f) ? be : 0.f;
        }
        __syncthreads();
#pragma unroll
        for (int k = 0; k < 16; k++) {
            float4 a4 = *(const float4*)&sxa[k][ty * 4];
            float4 A4 = *(const float4*)&sxA[k][ty * 4];
            float4 w4 = *(const float4*)&sxW[k][ty * 4];
            float4 p4 = *(const float4*)&spa[k][tx * 4];
            float4 P4 = *(const float4*)&spP[k][tx * 4];
            float4 v4 = *(const float4*)&spW[k][tx * 4];
            float av[4] = {a4.x, a4.y, a4.z, a4.w};
            float Av[4] = {A4.x, A4.y, A4.z, A4.w};
            float wv[4] = {w4.x, w4.y, w4.z, w4.w};
            float pv[4] = {p4.x, p4.y, p4.z, p4.w};
            float Pv[4] = {P4.x, P4.y, P4.z, P4.w};
            float vv[4] = {v4.x, v4.y, v4.z, v4.w};
#pragma unroll
            for (int i = 0; i < 4; i++)
#pragma unroll
                for (int j = 0; j < 4; j++) {
                    float m = fminf(av[i], pv[j]);
                    float t = acc[i][j];
                    t = fmaf(Av[i], Pv[j], t);
                    t = fmaf(wv[i], m, t);
                    t = fmaf(vv[j], m, t);
                    acc[i][j] = t;
                }
        }
        __syncthreads();
    }
    float rx[4], rp[4];
#pragma unroll
    for (int i = 0; i < 4; i++) rx[i] = al * Rx[bn + ty * 4 + i];
#pragma unroll
    for (int j = 0; j < 4; j++) rp[j] = be * Rp[bo + tx * 4 + j];
#pragma unroll
    for (int i = 0; i < 4; i++)
#pragma unroll
        for (int j = 0; j < 4; j++)
            out[(size_t)(bn + ty * 4 + i) * ldo + bo + tx * 4 + j] =
                acc[i][j] - rx[i] - rp[j];
}

__global__ __launch_bounds__(256) void tversky_qkv(
    const float* __restrict__ feat, const float* __restrict__ R,
    const float* __restrict__ tab, float* __restrict__ qkv)
{
    int z = blockIdx.z;
    const float* pf = feat + (size_t)(N_TOK + z * Dm) * Kf;
    const float* Rp = R + N_TOK + z * Dm;
    const float* t3 = tab + z * 3;
    float* out = qkv + (size_t)z * N_TOK * Dm;
    tversky_tile(feat, pf, R, Rp, t3[0], t3[1], t3[2],
                 blockIdx.y * 64, blockIdx.x * 64, out, Dm);
}

__global__ __launch_bounds__(256) void tversky_out(
    const float* __restrict__ cf, const float* __restrict__ Rcf,
    const float* __restrict__ feat, const float* __restrict__ R,
    const float* __restrict__ tab, float* __restrict__ out)
{
    const float* pf = feat + (size_t)(N_TOK + 3 * Dm) * Kf;
    const float* Rp = R + N_TOK + 3 * Dm;
    tversky_tile(cf, pf, Rcf, Rp, tab[9], tab[10], tab[11],
                 blockIdx.y * 64, blockIdx.x * 64, out, Dm);
}

// ---------------- flash attention: online softmax, k in 64-chunks -----------
// Block 256 (16x16), q-tile 32, grid (16 q-tiles, 16 z). regs capped for occ.
__global__ __launch_bounds__(256, 3) void attn_flash(
    const float* __restrict__ Q, const float* __restrict__ Km,
    const float* __restrict__ V, const int* __restrict__ mask,
    float* __restrict__ ctx)
{
    __shared__ float Qs[64][36];   // [d][q]
    __shared__ float Ks[64][68];   // [d][k] for K; reused as [k][d] for V
    __shared__ float Ps[32][68];   // probs chunk [q][k]
    int z = blockIdx.y;
    int b = z >> 3, h = z & 7;
    const float* Qg = Q  + (size_t)b * Sq * Dm + h * DK;
    const float* Kg = Km + (size_t)b * Sq * Dm + h * DK;
    const float* Vg = V  + (size_t)b * Sq * Dm + h * DK;
    const int*   mg = mask + (size_t)b * Sq * Sq;
    int bq = blockIdx.x * 32;
    int tx = threadIdx.x, ty = threadIdx.y;
    int tid = ty * 16 + tx;
    int r0 = bq + ty * 2, r1 = r0 + 1;

#pragma unroll
    for (int l = 0; l < 8; l++) {          // Qs: 32q x 64d
        int e = tid + l * 256;
        int m = e >> 6, d = e & 63;
        Qs[d][m] = Qg[(size_t)(bq + m) * Dm + d];
    }

    float out[2][4] = {};
    float mr0 = -INFINITY, mr1 = -INFINITY;
    float lr0 = 0.f, lr1 = 0.f;

    for (int kc = 0; kc < 8; kc++) {
        int bk = kc * 64;
#pragma unroll
        for (int l = 0; l < 16; l++) {     // Ks[d][k]
            int e = tid + l * 256;
            int kk = e >> 6, d = e & 63;
            Ks[d][kk] = Kg[(size_t)(bk + kk) * Dm + d];
        }
        __syncthreads();

        float S[2][4] = {};
#pragma unroll
        for (int d = 0; d < 64; d++) {
            float a0 = Qs[d][ty * 2];
            float a1 = Qs[d][ty * 2 + 1];
            float4 k4 = *(const float4*)&Ks[d][tx * 4];
            S[0][0] = fmaf(a0, k4.x, S[0][0]);
            S[0][1] = fmaf(a0, k4.y, S[0][1]);
            S[0][2] = fmaf(a0, k4.z, S[0][2]);
            S[0][3] = fmaf(a0, k4.w, S[0][3]);
            S[1][0] = fmaf(a1, k4.x, S[1][0]);
            S[1][1] = fmaf(a1, k4.y, S[1][1]);
            S[1][2] = fmaf(a1, k4.z, S[1][2]);
            S[1][3] = fmaf(a1, k4.w, S[1][3]);
        }
        __syncthreads();                   // done reading Ks

        // mask
        {
            int4 m40 = *(const int4*)&mg[(size_t)r0 * Sq + bk + tx * 4];
            int4 m41 = *(const int4*)&mg[(size_t)r1 * Sq + bk + tx * 4];
            if (m40.x == 0) S[0][0] = -INFINITY;
            if (m40.y == 0) S[0][1] = -INFINITY;
            if (m40.z == 0) S[0][2] = -INFINITY;
            if (m40.w == 0) S[0][3] = -INFINITY;
            if (m41.x == 0) S[1][0] = -INFINITY;
            if (m41.y == 0) S[1][1] = -INFINITY;
            if (m41.z == 0) S[1][2] = -INFINITY;
            if (m41.w == 0) S[1][3] = -INFINITY;
        }

        // chunk max per row (16 tx lanes = half-warp)
        float c0 = fmaxf(fmaxf(S[0][0], S[0][1]), fmaxf(S[0][2], S[0][3]));
        float c1 = fmaxf(fmaxf(S[1][0], S[1][1]), fmaxf(S[1][2], S[1][3]));
#pragma unroll
        for (int o = 8; o; o >>= 1) {
            c0 = fmaxf(c0, __shfl_xor_sync(0xffffffffu, c0, o));
            c1 = fmaxf(c1, __shfl_xor_sync(0xffffffffu, c1, o));
        }
        float mn0 = fmaxf(mr0, c0);
        float mn1 = fmaxf(mr1, c1);
        float sc0 = __expf((mr0 - mn0) * 0.125f);   // 0 on first chunk
        float sc1 = __expf((mr1 - mn1) * 0.125f);
        mr0 = mn0; mr1 = mn1;

        // P = exp((S - m)/8), chunk sums
        float p00 = __expf((S[0][0] - mn0) * 0.125f);
        float p01 = __expf((S[0][1] - mn0) * 0.125f);
        float p02 = __expf((S[0][2] - mn0) * 0.125f);
        float p03 = __expf((S[0][3] - mn0) * 0.125f);
        float p10 = __expf((S[1][0] - mn1) * 0.125f);
        float p11 = __expf((S[1][1] - mn1) * 0.125f);
        float p12 = __expf((S[1][2] - mn1) * 0.125f);
        float p13 = __expf((S[1][3] - mn1) * 0.125f);
        float s0 = p00 + p01 + p02 + p03;
        float s1 = p10 + p11 + p12 + p13;
#pragma unroll
        for (int o = 8; o; o >>= 1) {
            s0 += __shfl_xor_sync(0xffffffffu, s0, o);
            s1 += __shfl_xor_sync(0xffffffffu, s1, o);
        }
        lr0 = lr0 * sc0 + s0;
        lr1 = lr1 * sc1 + s1;
#pragma unroll
        for (int j = 0; j < 4; j++) { out[0][j] *= sc0; out[1][j] *= sc1; }

        *(float4*)&Ps[ty * 2][tx * 4]     = make_float4(p00, p01, p02, p03);
        *(float4*)&Ps[ty * 2 + 1][tx * 4] = make_float4(p10, p11, p12, p13);

#pragma unroll
        for (int l = 0; l < 16; l++) {     // Vs[k][d] into Ks
            int e = tid + l * 256;
            int kk = e >> 6, d = e & 63;
            Ks[kk][d] = Vg[(size_t)(bk + kk) * Dm + d];
        }
        __syncthreads();                   // Ps + V visible

#pragma unroll
        for (int k = 0; k < 64; k++) {
            float a0 = Ps[ty * 2][k];
            float a1 = Ps[ty * 2 + 1][k];
            float4 v4 = *(const float4*)&Ks[k][tx * 4];
            out[0][0] = fmaf(a0, v4.x, out[0][0]);
            out[0][1] = fmaf(a0, v4.y, out[0][1]);
            out[0][2] = fmaf(a0, v4.z, out[0][2]);
            out[0][3] = fmaf(a0, v4.w, out[0][3]);
            out[1][0] = fmaf(a1, v4.x, out[1][0]);
            out[1][1] = fmaf(a1, v4.y, out[1][1]);
            out[1][2] = fmaf(a1, v4.z, out[1][2]);
            out[1][3] = fmaf(a1, v4.w, out[1][3]);
        }
        __syncthreads();                   // done reading Ks/Ps
    }

    float i0 = 1.f / lr0, i1 = 1.f / lr1;
    float* cg = ctx + (size_t)b * Sq * Dm + h * DK;
    *(float4*)&cg[(size_t)r0 * Dm + tx * 4] =
        make_float4(out[0][0] * i0, out[0][1] * i0, out[0][2] * i0, out[0][3] * i0);
    *(float4*)&cg[(size_t)r1 * Dm + tx * 4] =
        make_float4(out[1][0] * i1, out[1][1] * i1, out[1][2] * i1, out[1][3] * i1);
}

// ---------------- launch ----------------------------------------------------
extern "C" void kernel_launch(void* const* d_in, const int* in_sizes, int n_in,
                              void* d_out, int out_size)
{
    const float* x     = (const float*)d_in[0];
    const int*   mask  = (const int*)d_in[1];
    const float* omega = (const float*)d_in[2];
    const float* Pq    = (const float*)d_in[3];
    const float* Pk    = (const float*)d_in[4];
    const float* Pv    = (const float*)d_in[5];
    const float* Po    = (const float*)d_in[6];
    const float* tab   = (const float*)d_in[7];
    float* out = (float*)d_out;

    float *p_feat, *p_R, *p_Rcf, *p_qkv, *p_ctx, *p_cfp, *p_cf;
    cudaGetSymbolAddress((void**)&p_feat, g_feat);
    cudaGetSymbolAddress((void**)&p_R, g_R);
    cudaGetSymbolAddress((void**)&p_Rcf, g_Rcf);
    cudaGetSymbolAddress((void**)&p_qkv, g_QKV);
    cudaGetSymbolAddress((void**)&p_ctx, g_ctx);
    cudaGetSymbolAddress((void**)&p_cfp, g_cfp);
    cudaGetSymbolAddress((void**)&p_cf, g_cf);

    float* p_Q = p_qkv;
    float* p_K = p_qkv + (size_t)N_TOK * Dm;
    float* p_V = p_qkv + (size_t)2 * N_TOK * Dm;

    dim3 blk(16, 16);

    // feature maps + row relu-sums
    feat_gemm<<<dim3(2, 96), blk>>>(x, Pq, Pk, Pv, Po, omega, p_feat);
    rowrelu<<<(N_TOK + 4 * Dm) / 8, dim3(32, 8)>>>(p_feat, p_R);

    // Q, K, V projections (min-trick)
    tversky_qkv<<<dim3(8, 16, 3), blk>>>(p_feat, p_R, tab, p_qkv);

    // flash attention
    attn_flash<<<dim3(16, 16), blk>>>(p_Q, p_K, p_V, mask, p_ctx);

    // output projection
    gemm_split<<<dim3(2, 16, 8), blk>>>(p_ctx, omega, p_cfp);
    add8<<<(N_TOK * Kf / 4) / 256, 256>>>(p_cfp, p_cf);
    rowrelu<<<N_TOK / 8, dim3(32, 8)>>>(p_cf, p_Rcf);
    tversky_out<<<dim3(8, 16), blk>>>(p_cf, p_Rcf, p_feat, p_R, tab, out);
}

// round 10
// speedup vs baseline: 1.3169x; 1.0009x over previous
#include <cuda_runtime.h>
#include <math.h>

#define N_TOK 1024
#define Dm 512
#define Kf 128
#define Sq 512
#define DK 64

// ---------------- scratch ---------------------------------------------------
__device__ float g_feat[(N_TOK + 4 * Dm) * Kf];
__device__ float g_R[N_TOK + 4 * Dm];
__device__ float g_Rcf[N_TOK];
__device__ float g_QKV[3 * N_TOK * Dm];
__device__ float g_ctx[N_TOK * Dm];
__device__ float g_pout[2 * 16 * Sq * DK];   // kv-split partial outputs
__device__ float g_pml[2 * 16 * Sq * 2];     // kv-split partial (m, l)
__device__ float g_cfp[8][N_TOK * Kf];
__device__ float g_cf[N_TOK * Kf];

// ---------------- feature GEMM: feat = [x;Pq;Pk;Pv;Po] @ omega --------------
__global__ __launch_bounds__(256) void feat_gemm(
    const float* __restrict__ x,  const float* __restrict__ Pq,
    const float* __restrict__ Pk, const float* __restrict__ Pv,
    const float* __restrict__ Po, const float* __restrict__ omega,
    float* __restrict__ feat)
{
    __shared__ float As[32][36];
    __shared__ float Bs[32][68];
    int tx = threadIdx.x, ty = threadIdx.y;
    int tid = ty * 16 + tx;
    int bm = blockIdx.y * 32, bn = blockIdx.x * 64;

    const float* A;
    int row0;
    if (bm < N_TOK) { A = x; row0 = bm; }
    else {
        int s = (bm - N_TOK) >> 9;
        const float* Ps[4] = {Pq, Pk, Pv, Po};
        A = Ps[s]; row0 = (bm - N_TOK) & 511;
    }

    float acc[2][4] = {};
    for (int k0 = 0; k0 < Dm; k0 += 32) {
#pragma unroll
        for (int l = 0; l < 4; l++) {
            int e = tid + l * 256;
            int i = e >> 5, j = e & 31;
            As[j][i] = A[(size_t)(row0 + i) * Dm + k0 + j];
        }
#pragma unroll
        for (int l = 0; l < 8; l++) {
            int e = tid + l * 256;
            int kk = e >> 6, j = e & 63;
            Bs[kk][j] = omega[(size_t)(k0 + kk) * Kf + bn + j];
        }
        __syncthreads();
#pragma unroll
        for (int k = 0; k < 32; k++) {
            float2 a2 = *(const float2*)&As[k][ty * 2];
            float4 b4 = *(const float4*)&Bs[k][tx * 4];
            acc[0][0] = fmaf(a2.x, b4.x, acc[0][0]);
            acc[0][1] = fmaf(a2.x, b4.y, acc[0][1]);
            acc[0][2] = fmaf(a2.x, b4.z, acc[0][2]);
            acc[0][3] = fmaf(a2.x, b4.w, acc[0][3]);
            acc[1][0] = fmaf(a2.y, b4.x, acc[1][0]);
            acc[1][1] = fmaf(a2.y, b4.y, acc[1][1]);
            acc[1][2] = fmaf(a2.y, b4.z, acc[1][2]);
            acc[1][3] = fmaf(a2.y, b4.w, acc[1][3]);
        }
        __syncthreads();
    }
#pragma unroll
    for (int i = 0; i < 2; i++)
#pragma unroll
        for (int j = 0; j < 4; j++)
            feat[(size_t)(bm + ty * 2 + i) * Kf + bn + tx * 4 + j] = acc[i][j];
}

// ---------------- split-K GEMM (K split 8) ----------------------------------
__global__ __launch_bounds__(256) void gemm_split(
    const float* __restrict__ A, const float* __restrict__ B,
    float* __restrict__ Cp)
{
    __shared__ float As[32][68];
    __shared__ float Bs[32][68];
    int tx = threadIdx.x, ty = threadIdx.y;
    int tid = ty * 16 + tx;
    int bm = blockIdx.y * 64, bn = blockIdx.x * 64;
    int kbase = blockIdx.z * 64;
    float* C = Cp + (size_t)blockIdx.z * N_TOK * Kf;
    float acc[4][4] = {};
    for (int k0 = kbase; k0 < kbase + 64; k0 += 32) {
#pragma unroll
        for (int l = 0; l < 8; l++) {
            int e = tid + l * 256;
            int i = e >> 5, j = e & 31;
            As[j][i] = A[(size_t)(bm + i) * Dm + k0 + j];
        }
#pragma unroll
        for (int l = 0; l < 8; l++) {
            int e = tid + l * 256;
            int kk = e >> 6, j = e & 63;
            Bs[kk][j] = B[(size_t)(k0 + kk) * Kf + bn + j];
        }
        __syncthreads();
#pragma unroll
        for (int k = 0; k < 32; k++) {
            float4 a4 = *(const float4*)&As[k][ty * 4];
            float4 b4 = *(const float4*)&Bs[k][tx * 4];
            float av[4] = {a4.x, a4.y, a4.z, a4.w};
            float bv[4] = {b4.x, b4.y, b4.z, b4.w};
#pragma unroll
            for (int i = 0; i < 4; i++)
#pragma unroll
                for (int j = 0; j < 4; j++)
                    acc[i][j] = fmaf(av[i], bv[j], acc[i][j]);
        }
        __syncthreads();
    }
#pragma unroll
    for (int i = 0; i < 4; i++)
#pragma unroll
        for (int j = 0; j < 4; j++)
            C[(size_t)(bm + ty * 4 + i) * Kf + bn + tx * 4 + j] = acc[i][j];
}

__global__ __launch_bounds__(256) void add8(const float* __restrict__ Cp,
                                            float* __restrict__ C)
{
    int idx = blockIdx.x * 256 + threadIdx.x;
    const size_t n = (size_t)N_TOK * Kf;
    float4 r = ((const float4*)Cp)[idx];
#pragma unroll
    for (int z = 1; z < 8; z++) {
        float4 a = ((const float4*)(Cp + (size_t)z * n))[idx];
        r.x += a.x; r.y += a.y; r.z += a.z; r.w += a.w;
    }
    ((float4*)C)[idx] = r;
}

// ---------------- row relu-sums ---------------------------------------------
__global__ __launch_bounds__(256) void rowrelu(const float* __restrict__ f,
                                               float* __restrict__ R)
{
    int row = blockIdx.x * 8 + threadIdx.y;
    int lane = threadIdx.x;
    float4 v = ((const float4*)(f + (size_t)row * Kf))[lane];
    float s = fmaxf(v.x, 0.f) + fmaxf(v.y, 0.f) + fmaxf(v.z, 0.f) + fmaxf(v.w, 0.f);
#pragma unroll
    for (int o = 16; o; o >>= 1) s += __shfl_xor_sync(0xffffffffu, s, o);
    if (lane == 0) R[row] = s;
}

// ---------------- Tversky 64x64 tile, min-trick -----------------------------
__device__ __forceinline__ void tversky_tile(
    const float* __restrict__ xf, const float* __restrict__ pf,
    const float* __restrict__ Rx, const float* __restrict__ Rp,
    float th, float al, float be, int bn, int bo,
    float* __restrict__ out, int ldo)
{
    __shared__ float sxa[16][68], sxA[16][68], sxW[16][68];
    __shared__ float spa[16][68], spP[16][68], spW[16][68];
    int tx = threadIdx.x, ty = threadIdx.y;
    int tid = ty * 16 + tx;
    float acc[4][4] = {};
    for (int k0 = 0; k0 < Kf; k0 += 16) {
#pragma unroll
        for (int l = 0; l < 4; l++) {
            int e = tid + l * 256;
            int i = e >> 4, j = e & 15;
            float a = xf[(size_t)(bn + i) * Kf + k0 + j];
            sxa[j][i] = a;
            sxA[j][i] = th * fmaxf(a, 0.f);
            sxW[j][i] = (a > 0.f) ? al : 0.f;
            float p = pf[(size_t)(bo + i) * Kf + k0 + j];
            spa[j][i] = p;
            spP[j][i] = fmaxf(p, 0.f);
            spW[j][i] = (p > 0.f) ? be : 0.f;
        }
        __syncthreads();
#pragma unroll
        for (int k = 0; k < 16; k++) {
            float4 a4 = *(const float4*)&sxa[k][ty * 4];
            float4 A4 = *(const float4*)&sxA[k][ty * 4];
            float4 w4 = *(const float4*)&sxW[k][ty * 4];
            float4 p4 = *(const float4*)&spa[k][tx * 4];
            float4 P4 = *(const float4*)&spP[k][tx * 4];
            float4 v4 = *(const float4*)&spW[k][tx * 4];
            float av[4] = {a4.x, a4.y, a4.z, a4.w};
            float Av[4] = {A4.x, A4.y, A4.z, A4.w};
            float wv[4] = {w4.x, w4.y, w4.z, w4.w};
            float pv[4] = {p4.x, p4.y, p4.z, p4.w};
            float Pv[4] = {P4.x, P4.y, P4.z, P4.w};
            float vv[4] = {v4.x, v4.y, v4.z, v4.w};
#pragma unroll
            for (int i = 0; i < 4; i++)
#pragma unroll
                for (int j = 0; j < 4; j++) {
                    float m = fminf(av[i], pv[j]);
                    float t = acc[i][j];
                    t = fmaf(Av[i], Pv[j], t);
                    t = fmaf(wv[i], m, t);
                    t = fmaf(vv[j], m, t);
                    acc[i][j] = t;
                }
        }
        __syncthreads();
    }
    float rx[4], rp[4];
#pragma unroll
    for (int i = 0; i < 4; i++) rx[i] = al * Rx[bn + ty * 4 + i];
#pragma unroll
    for (int j = 0; j < 4; j++) rp[j] = be * Rp[bo + tx * 4 + j];
#pragma unroll
    for (int i = 0; i < 4; i++)
#pragma unroll
        for (int j = 0; j < 4; j++)
            out[(size_t)(bn + ty * 4 + i) * ldo + bo + tx * 4 + j] =
                acc[i][j] - rx[i] - rp[j];
}

__global__ __launch_bounds__(256) void tversky_qkv(
    const float* __restrict__ feat, const float* __restrict__ R,
    const float* __restrict__ tab, float* __restrict__ qkv)
{
    int z = blockIdx.z;
    const float* pf = feat + (size_t)(N_TOK + z * Dm) * Kf;
    const float* Rp = R + N_TOK + z * Dm;
    const float* t3 = tab + z * 3;
    float* out = qkv + (size_t)z * N_TOK * Dm;
    tversky_tile(feat, pf, R, Rp, t3[0], t3[1], t3[2],
                 blockIdx.y * 64, blockIdx.x * 64, out, Dm);
}

__global__ __launch_bounds__(256) void tversky_out(
    const float* __restrict__ cf, const float* __restrict__ Rcf,
    const float* __restrict__ feat, const float* __restrict__ R,
    const float* __restrict__ tab, float* __restrict__ out)
{
    const float* pf = feat + (size_t)(N_TOK + 3 * Dm) * Kf;
    const float* Rp = R + N_TOK + 3 * Dm;
    tversky_tile(cf, pf, Rcf, Rp, tab[9], tab[10], tab[11],
                 blockIdx.y * 64, blockIdx.x * 64, out, Dm);
}

// ---------------- flash attention, kv-split 2 --------------------------------
// Grid (16 q-tiles, 16 z, 2 kv). Each block: 4 chunks of 64 k.
// Writes unnormalized partial out + (m, l).
__global__ __launch_bounds__(256, 3) void attn_part(
    const float* __restrict__ Q, const float* __restrict__ Km,
    const float* __restrict__ V, const int* __restrict__ mask,
    float* __restrict__ pout, float* __restrict__ pml)
{
    __shared__ float Qs[64][36];
    __shared__ float Ks[64][68];
    __shared__ float Ps[32][68];
    int z = blockIdx.y;
    int sp = blockIdx.z;
    int b = z >> 3, h = z & 7;
    const float* Qg = Q  + (size_t)b * Sq * Dm + h * DK;
    const float* Kg = Km + (size_t)b * Sq * Dm + h * DK;
    const float* Vg = V  + (size_t)b * Sq * Dm + h * DK;
    const int*   mg = mask + (size_t)b * Sq * Sq;
    int bq = blockIdx.x * 32;
    int tx = threadIdx.x, ty = threadIdx.y;
    int tid = ty * 16 + tx;
    int r0 = bq + ty * 2, r1 = r0 + 1;

#pragma unroll
    for (int l = 0; l < 8; l++) {
        int e = tid + l * 256;
        int m = e >> 6, d = e & 63;
        Qs[d][m] = Qg[(size_t)(bq + m) * Dm + d];
    }

    float out[2][4] = {};
    float mr0 = -INFINITY, mr1 = -INFINITY;
    float lr0 = 0.f, lr1 = 0.f;

    for (int kc = 0; kc < 4; kc++) {
        int bk = (sp * 4 + kc) * 64;
#pragma unroll
        for (int l = 0; l < 16; l++) {
            int e = tid + l * 256;
            int kk = e >> 6, d = e & 63;
            Ks[d][kk] = Kg[(size_t)(bk + kk) * Dm + d];
        }
        __syncthreads();

        float S[2][4] = {};
#pragma unroll
        for (int d = 0; d < 64; d++) {
            float a0 = Qs[d][ty * 2];
            float a1 = Qs[d][ty * 2 + 1];
            float4 k4 = *(const float4*)&Ks[d][tx * 4];
            S[0][0] = fmaf(a0, k4.x, S[0][0]);
            S[0][1] = fmaf(a0, k4.y, S[0][1]);
            S[0][2] = fmaf(a0, k4.z, S[0][2]);
            S[0][3] = fmaf(a0, k4.w, S[0][3]);
            S[1][0] = fmaf(a1, k4.x, S[1][0]);
            S[1][1] = fmaf(a1, k4.y, S[1][1]);
            S[1][2] = fmaf(a1, k4.z, S[1][2]);
            S[1][3] = fmaf(a1, k4.w, S[1][3]);
        }
        __syncthreads();

        {
            int4 m40 = *(const int4*)&mg[(size_t)r0 * Sq + bk + tx * 4];
            int4 m41 = *(const int4*)&mg[(size_t)r1 * Sq + bk + tx * 4];
            if (m40.x == 0) S[0][0] = -INFINITY;
            if (m40.y == 0) S[0][1] = -INFINITY;
            if (m40.z == 0) S[0][2] = -INFINITY;
            if (m40.w == 0) S[0][3] = -INFINITY;
            if (m41.x == 0) S[1][0] = -INFINITY;
            if (m41.y == 0) S[1][1] = -INFINITY;
            if (m41.z == 0) S[1][2] = -INFINITY;
            if (m41.w == 0) S[1][3] = -INFINITY;
        }

        float c0 = fmaxf(fmaxf(S[0][0], S[0][1]), fmaxf(S[0][2], S[0][3]));
        float c1 = fmaxf(fmaxf(S[1][0], S[1][1]), fmaxf(S[1][2], S[1][3]));
#pragma unroll
        for (int o = 8; o; o >>= 1) {
            c0 = fmaxf(c0, __shfl_xor_sync(0xffffffffu, c0, o));
            c1 = fmaxf(c1, __shfl_xor_sync(0xffffffffu, c1, o));
        }
        float mn0 = fmaxf(mr0, c0);
        float mn1 = fmaxf(mr1, c1);
        float sc0 = __expf((mr0 - mn0) * 0.125f);
        float sc1 = __expf((mr1 - mn1) * 0.125f);
        mr0 = mn0; mr1 = mn1;

        float p00 = __expf((S[0][0] - mn0) * 0.125f);
        float p01 = __expf((S[0][1] - mn0) * 0.125f);
        float p02 = __expf((S[0][2] - mn0) * 0.125f);
        float p03 = __expf((S[0][3] - mn0) * 0.125f);
        float p10 = __expf((S[1][0] - mn1) * 0.125f);
        float p11 = __expf((S[1][1] - mn1) * 0.125f);
        float p12 = __expf((S[1][2] - mn1) * 0.125f);
        float p13 = __expf((S[1][3] - mn1) * 0.125f);
        float s0 = p00 + p01 + p02 + p03;
        float s1 = p10 + p11 + p12 + p13;
#pragma unroll
        for (int o = 8; o; o >>= 1) {
            s0 += __shfl_xor_sync(0xffffffffu, s0, o);
            s1 += __shfl_xor_sync(0xffffffffu, s1, o);
        }
        lr0 = lr0 * sc0 + s0;
        lr1 = lr1 * sc1 + s1;
#pragma unroll
        for (int j = 0; j < 4; j++) { out[0][j] *= sc0; out[1][j] *= sc1; }

        *(float4*)&Ps[ty * 2][tx * 4]     = make_float4(p00, p01, p02, p03);
        *(float4*)&Ps[ty * 2 + 1][tx * 4] = make_float4(p10, p11, p12, p13);

#pragma unroll
        for (int l = 0; l < 16; l++) {
            int e = tid + l * 256;
            int kk = e >> 6, d = e & 63;
            Ks[kk][d] = Vg[(size_t)(bk + kk) * Dm + d];
        }
        __syncthreads();

#pragma unroll
        for (int k = 0; k < 64; k++) {
            float a0 = Ps[ty * 2][k];
            float a1 = Ps[ty * 2 + 1][k];
            float4 v4 = *(const float4*)&Ks[k][tx * 4];
            out[0][0] = fmaf(a0, v4.x, out[0][0]);
            out[0][1] = fmaf(a0, v4.y, out[0][1]);
            out[0][2] = fmaf(a0, v4.z, out[0][2]);
            out[0][3] = fmaf(a0, v4.w, out[0][3]);
            out[1][0] = fmaf(a1, v4.x, out[1][0]);
            out[1][1] = fmaf(a1, v4.y, out[1][1]);
            out[1][2] = fmaf(a1, v4.z, out[1][2]);
            out[1][3] = fmaf(a1, v4.w, out[1][3]);
        }
        __syncthreads();
    }

    // write unnormalized partials: pout[((sp*16+z)*Sq + q)*DK + d]
    float* po = pout + ((size_t)(sp * 16 + z) * Sq) * DK;
    *(float4*)&po[(size_t)r0 * DK + tx * 4] =
        make_float4(out[0][0], out[0][1], out[0][2], out[0][3]);
    *(float4*)&po[(size_t)r1 * DK + tx * 4] =
        make_float4(out[1][0], out[1][1], out[1][2], out[1][3]);
    if (tx == 0) {
        float* pm = pml + ((size_t)(sp * 16 + z) * Sq) * 2;
        pm[r0 * 2] = mr0; pm[r0 * 2 + 1] = lr0;
        pm[r1 * 2] = mr1; pm[r1 * 2 + 1] = lr1;
    }
}

// combine two kv-split partials -> ctx. Block (64, 4): 4 rows x 64 d.
__global__ __launch_bounds__(256) void attn_combine(
    const float* __restrict__ pout, const float* __restrict__ pml,
    float* __restrict__ ctx)
{
    int row = blockIdx.x * 4 + threadIdx.y;   // 0 .. 16*Sq-1 (z*Sq + q)
    int d = threadIdx.x;
    int z = row >> 9, q = row & 511;
    int b = z >> 3, h = z & 7;
    const float* pm0 = pml + ((size_t)z * Sq + q) * 2;
    const float* pm1 = pml + ((size_t)(16 + z) * Sq + q) * 2;
    float m0 = pm0[0], l0 = pm0[1];
    float m1 = pm1[0], l1 = pm1[1];
    float mm = fmaxf(m0, m1);
    float w0 = __expf((m0 - mm) * 0.125f);
    float w1 = __expf((m1 - mm) * 0.125f);
    float inv = 1.f / (l0 * w0 + l1 * w1);
    float o0 = pout[((size_t)z * Sq + q) * DK + d];
    float o1 = pout[((size_t)(16 + z) * Sq + q) * DK + d];
    ctx[(size_t)b * Sq * Dm + (size_t)q * Dm + h * DK + d] =
        (o0 * w0 + o1 * w1) * inv;
}

// ---------------- launch ----------------------------------------------------
extern "C" void kernel_launch(void* const* d_in, const int* in_sizes, int n_in,
                              void* d_out, int out_size)
{
    const float* x     = (const float*)d_in[0];
    const int*   mask  = (const int*)d_in[1];
    const float* omega = (const float*)d_in[2];
    const float* Pq    = (const float*)d_in[3];
    const float* Pk    = (const float*)d_in[4];
    const float* Pv    = (const float*)d_in[5];
    const float* Po    = (const float*)d_in[6];
    const float* tab   = (const float*)d_in[7];
    float* out = (float*)d_out;

    float *p_feat, *p_R, *p_Rcf, *p_qkv, *p_ctx, *p_po, *p_pm, *p_cfp, *p_cf;
    cudaGetSymbolAddress((void**)&p_feat, g_feat);
    cudaGetSymbolAddress((void**)&p_R, g_R);
    cudaGetSymbolAddress((void**)&p_Rcf, g_Rcf);
    cudaGetSymbolAddress((void**)&p_qkv, g_QKV);
    cudaGetSymbolAddress((void**)&p_ctx, g_ctx);
    cudaGetSymbolAddress((void**)&p_po, g_pout);
    cudaGetSymbolAddress((void**)&p_pm, g_pml);
    cudaGetSymbolAddress((void**)&p_cfp, g_cfp);
    cudaGetSymbolAddress((void**)&p_cf, g_cf);

    float* p_Q = p_qkv;
    float* p_K = p_qkv + (size_t)N_TOK * Dm;
    float* p_V = p_qkv + (size_t)2 * N_TOK * Dm;

    dim3 blk(16, 16);

    feat_gemm<<<dim3(2, 96), blk>>>(x, Pq, Pk, Pv, Po, omega, p_feat);
    rowrelu<<<(N_TOK + 4 * Dm) / 8, dim3(32, 8)>>>(p_feat, p_R);

    tversky_qkv<<<dim3(8, 16, 3), blk>>>(p_feat, p_R, tab, p_qkv);

    attn_part<<<dim3(16, 16, 2), blk>>>(p_Q, p_K, p_V, mask, p_po, p_pm);
    attn_combine<<<16 * Sq / 4, dim3(64, 4)>>>(p_po, p_pm, p_ctx);

    gemm_split<<<dim3(2, 16, 8), blk>>>(p_ctx, omega, p_cfp);
    add8<<<(N_TOK * Kf / 4) / 256, 256>>>(p_cfp, p_cf);
    rowrelu<<<N_TOK / 8, dim3(32, 8)>>>(p_cf, p_Rcf);
    tversky_out<<<dim3(8, 16), blk>>>(p_cf, p_Rcf, p_feat, p_R, tab, out);
}

// round 12
// speedup vs baseline: 1.4866x; 1.1289x over previous
#include <cuda_runtime.h>
#include <math.h>

#define N_TOK 1024
#define Dm 512
#define Kf 128
#define Sq 512
#define DK 64
#define NSPLIT 4
#define ATTN_SMEM (3 * 64 * 68 * 4)

// ---------------- scratch ---------------------------------------------------
__device__ float g_feat[(N_TOK + 4 * Dm) * Kf];
__device__ float g_R[N_TOK + 4 * Dm];
__device__ float g_Rcf[N_TOK];
__device__ float g_QKV[3 * N_TOK * Dm];
__device__ float g_ctx[N_TOK * Dm];
__device__ float g_pout[NSPLIT * 16 * Sq * DK];
__device__ float g_pml[NSPLIT * 16 * Sq * 2];
__device__ float g_cfp[8][N_TOK * Kf];
__device__ float g_cf[N_TOK * Kf];

// ---------------- feature GEMM: feat = [x;Pq;Pk;Pv;Po] @ omega --------------
__global__ __launch_bounds__(256) void feat_gemm(
    const float* __restrict__ x,  const float* __restrict__ Pq,
    const float* __restrict__ Pk, const float* __restrict__ Pv,
    const float* __restrict__ Po, const float* __restrict__ omega,
    float* __restrict__ feat)
{
    __shared__ float As[32][36];
    __shared__ float Bs[32][68];
    int tx = threadIdx.x, ty = threadIdx.y;
    int tid = ty * 16 + tx;
    int bm = blockIdx.y * 32, bn = blockIdx.x * 64;

    const float* A;
    int row0;
    if (bm < N_TOK) { A = x; row0 = bm; }
    else {
        int s = (bm - N_TOK) >> 9;
        const float* Ps[4] = {Pq, Pk, Pv, Po};
        A = Ps[s]; row0 = (bm - N_TOK) & 511;
    }

    float acc[2][4] = {};
    for (int k0 = 0; k0 < Dm; k0 += 32) {
#pragma unroll
        for (int l = 0; l < 4; l++) {
            int e = tid + l * 256;
            int i = e >> 5, j = e & 31;
            As[j][i] = A[(size_t)(row0 + i) * Dm + k0 + j];
        }
#pragma unroll
        for (int l = 0; l < 8; l++) {
            int e = tid + l * 256;
            int kk = e >> 6, j = e & 63;
            Bs[kk][j] = omega[(size_t)(k0 + kk) * Kf + bn + j];
        }
        __syncthreads();
#pragma unroll
        for (int k = 0; k < 32; k++) {
            float2 a2 = *(const float2*)&As[k][ty * 2];
            float4 b4 = *(const float4*)&Bs[k][tx * 4];
            acc[0][0] = fmaf(a2.x, b4.x, acc[0][0]);
            acc[0][1] = fmaf(a2.x, b4.y, acc[0][1]);
            acc[0][2] = fmaf(a2.x, b4.z, acc[0][2]);
            acc[0][3] = fmaf(a2.x, b4.w, acc[0][3]);
            acc[1][0] = fmaf(a2.y, b4.x, acc[1][0]);
            acc[1][1] = fmaf(a2.y, b4.y, acc[1][1]);
            acc[1][2] = fmaf(a2.y, b4.z, acc[1][2]);
            acc[1][3] = fmaf(a2.y, b4.w, acc[1][3]);
        }
        __syncthreads();
    }
#pragma unroll
    for (int i = 0; i < 2; i++)
#pragma unroll
        for (int j = 0; j < 4; j++)
            feat[(size_t)(bm + ty * 2 + i) * Kf + bn + tx * 4 + j] = acc[i][j];
}

// ---------------- split-K GEMM (K split 8) ----------------------------------
__global__ __launch_bounds__(256) void gemm_split(
    const float* __restrict__ A, const float* __restrict__ B,
    float* __restrict__ Cp)
{
    __shared__ float As[32][68];
    __shared__ float Bs[32][68];
    int tx = threadIdx.x, ty = threadIdx.y;
    int tid = ty * 16 + tx;
    int bm = blockIdx.y * 64, bn = blockIdx.x * 64;
    int kbase = blockIdx.z * 64;
    float* C = Cp + (size_t)blockIdx.z * N_TOK * Kf;
    float acc[4][4] = {};
    for (int k0 = kbase; k0 < kbase + 64; k0 += 32) {
#pragma unroll
        for (int l = 0; l < 8; l++) {
            int e = tid + l * 256;
            int i = e >> 5, j = e & 31;
            As[j][i] = A[(size_t)(bm + i) * Dm + k0 + j];
        }
#pragma unroll
        for (int l = 0; l < 8; l++) {
            int e = tid + l * 256;
            int kk = e >> 6, j = e & 63;
            Bs[kk][j] = B[(size_t)(k0 + kk) * Kf + bn + j];
        }
        __syncthreads();
#pragma unroll
        for (int k = 0; k < 32; k++) {
            float4 a4 = *(const float4*)&As[k][ty * 4];
            float4 b4 = *(const float4*)&Bs[k][tx * 4];
            float av[4] = {a4.x, a4.y, a4.z, a4.w};
            float bv[4] = {b4.x, b4.y, b4.z, b4.w};
#pragma unroll
            for (int i = 0; i < 4; i++)
#pragma unroll
                for (int j = 0; j < 4; j++)
                    acc[i][j] = fmaf(av[i], bv[j], acc[i][j]);
        }
        __syncthreads();
    }
#pragma unroll
    for (int i = 0; i < 4; i++)
#pragma unroll
        for (int j = 0; j < 4; j++)
            C[(size_t)(bm + ty * 4 + i) * Kf + bn + tx * 4 + j] = acc[i][j];
}

__global__ __launch_bounds__(256) void add8(const float* __restrict__ Cp,
                                            float* __restrict__ C)
{
    int idx = blockIdx.x * 256 + threadIdx.x;
    const size_t n = (size_t)N_TOK * Kf;
    float4 r = ((const float4*)Cp)[idx];
#pragma unroll
    for (int z = 1; z < 8; z++) {
        float4 a = ((const float4*)(Cp + (size_t)z * n))[idx];
        r.x += a.x; r.y += a.y; r.z += a.z; r.w += a.w;
    }
    ((float4*)C)[idx] = r;
}

// ---------------- row relu-sums ---------------------------------------------
__global__ __launch_bounds__(256) void rowrelu(const float* __restrict__ f,
                                               float* __restrict__ R)
{
    int row = blockIdx.x * 8 + threadIdx.y;
    int lane = threadIdx.x;
    float4 v = ((const float4*)(f + (size_t)row * Kf))[lane];
    float s = fmaxf(v.x, 0.f) + fmaxf(v.y, 0.f) + fmaxf(v.z, 0.f) + fmaxf(v.w, 0.f);
#pragma unroll
    for (int o = 16; o; o >>= 1) s += __shfl_xor_sync(0xffffffffu, s, o);
    if (lane == 0) R[row] = s;
}

// ---------------- Tversky 64x64 tile, min-trick -----------------------------
__device__ __forceinline__ void tversky_tile(
    const float* __restrict__ xf, const float* __restrict__ pf,
    const float* __restrict__ Rx, const float* __restrict__ Rp,
    float th, float al, float be, int bn, int bo,
    float* __restrict__ out, int ldo)
{
    __shared__ float sxa[16][68], sxA[16][68], sxW[16][68];
    __shared__ float spa[16][68], spP[16][68], spW[16][68];
    int tx = threadIdx.x, ty = threadIdx.y;
    int tid = ty * 16 + tx;
    float acc[4][4] = {};
    for (int k0 = 0; k0 < Kf; k0 += 16) {
#pragma unroll
        for (int l = 0; l < 4; l++) {
            int e = tid + l * 256;
            int i = e >> 4, j = e & 15;
            float a = xf[(size_t)(bn + i) * Kf + k0 + j];
            sxa[j][i] = a;
            sxA[j][i] = th * fmaxf(a, 0.f);
            sxW[j][i] = (a > 0.f) ? al : 0.f;
            float p = pf[(size_t)(bo + i) * Kf + k0 + j];
            spa[j][i] = p;
            spP[j][i] = fmaxf(p, 0.f);
            spW[j][i] = (p > 0.f) ? be : 0.f;
        }
        __syncthreads();
#pragma unroll
        for (int k = 0; k < 16; k++) {
            float4 a4 = *(const float4*)&sxa[k][ty * 4];
            float4 A4 = *(const float4*)&sxA[k][ty * 4];
            float4 w4 = *(const float4*)&sxW[k][ty * 4];
            float4 p4 = *(const float4*)&spa[k][tx * 4];
            float4 P4 = *(const float4*)&spP[k][tx * 4];
            float4 v4 = *(const float4*)&spW[k][tx * 4];
            float av[4] = {a4.x, a4.y, a4.z, a4.w};
            float Av[4] = {A4.x, A4.y, A4.z, A4.w};
            float wv[4] = {w4.x, w4.y, w4.z, w4.w};
            float pv[4] = {p4.x, p4.y, p4.z, p4.w};
            float Pv[4] = {P4.x, P4.y, P4.z, P4.w};
            float vv[4] = {v4.x, v4.y, v4.z, v4.w};
#pragma unroll
            for (int i = 0; i < 4; i++)
#pragma unroll
                for (int j = 0; j < 4; j++) {
                    float m = fminf(av[i], pv[j]);
                    float t = acc[i][j];
                    t = fmaf(Av[i], Pv[j], t);
                    t = fmaf(wv[i], m, t);
                    t = fmaf(vv[j], m, t);
                    acc[i][j] = t;
                }
        }
        __syncthreads();
    }
    float rx[4], rp[4];
#pragma unroll
    for (int i = 0; i < 4; i++) rx[i] = al * Rx[bn + ty * 4 + i];
#pragma unroll
    for (int j = 0; j < 4; j++) rp[j] = be * Rp[bo + tx * 4 + j];
#pragma unroll
    for (int i = 0; i < 4; i++)
#pragma unroll
        for (int j = 0; j < 4; j++)
            out[(size_t)(bn + ty * 4 + i) * ldo + bo + tx * 4 + j] =
                acc[i][j] - rx[i] - rp[j];
}

__global__ __launch_bounds__(256) void tversky_qkv(
    const float* __restrict__ feat, const float* __restrict__ R,
    const float* __restrict__ tab, float* __restrict__ qkv)
{
    int z = blockIdx.z;
    const float* pf = feat + (size_t)(N_TOK + z * Dm) * Kf;
    const float* Rp = R + N_TOK + z * Dm;
    const float* t3 = tab + z * 3;
    float* out = qkv + (size_t)z * N_TOK * Dm;
    tversky_tile(feat, pf, R, Rp, t3[0], t3[1], t3[2],
                 blockIdx.y * 64, blockIdx.x * 64, out, Dm);
}

__global__ __launch_bounds__(256) void tversky_out(
    const float* __restrict__ cf, const float* __restrict__ Rcf,
    const float* __restrict__ feat, const float* __restrict__ R,
    const float* __restrict__ tab, float* __restrict__ out)
{
    const float* pf = feat + (size_t)(N_TOK + 3 * Dm) * Kf;
    const float* Rp = R + N_TOK + 3 * Dm;
    tversky_tile(cf, pf, Rcf, Rp, tab[9], tab[10], tab[11],
                 blockIdx.y * 64, blockIdx.x * 64, out, Dm);
}

// ---------------- flash attention, 4x4 micro-tile, kv-split 4 ----------------
// Grid (8 q-tiles of 64, 16 z, 4 kv-splits of 128 k = 2 chunks).
// Dynamic smem: Qs[64][68] | Ks[64][68] | Pst[64][68]  (52224 bytes)
__global__ __launch_bounds__(256) void attn_part(
    const float* __restrict__ Q, const float* __restrict__ Km,
    const float* __restrict__ V, const int* __restrict__ mask,
    float* __restrict__ pout, float* __restrict__ pml)
{
    extern __shared__ float smem[];
    float (*Qs)[68]  = (float (*)[68])smem;                 // [d][q]
    float (*Ks)[68]  = (float (*)[68])(smem + 64 * 68);     // [d][k] / [k][d]
    float (*Pst)[68] = (float (*)[68])(smem + 2 * 64 * 68); // probs^T [k][q]
    int z = blockIdx.y;
    int sp = blockIdx.z;
    int b = z >> 3, h = z & 7;
    const float* Qg = Q  + (size_t)b * Sq * Dm + h * DK;
    const float* Kg = Km + (size_t)b * Sq * Dm + h * DK;
    const float* Vg = V  + (size_t)b * Sq * Dm + h * DK;
    const int*   mg = mask + (size_t)b * Sq * Sq;
    int bq = blockIdx.x * 64;
    int tx = threadIdx.x, ty = threadIdx.y;
    int tid = ty * 16 + tx;

#pragma unroll
    for (int l = 0; l < 16; l++) {         // Qs: 64q x 64d
        int e = tid + l * 256;
        int m = e >> 6, d = e & 63;
        Qs[d][m] = Qg[(size_t)(bq + m) * Dm + d];
    }

    float out[4][4] = {};
    float mr[4] = {-INFINITY, -INFINITY, -INFINITY, -INFINITY};
    float lr[4] = {};

    for (int kc = 0; kc < 2; kc++) {
        int bk = sp * 128 + kc * 64;
#pragma unroll
        for (int l = 0; l < 16; l++) {     // Ks[d][k]
            int e = tid + l * 256;
            int kk = e >> 6, d = e & 63;
            Ks[d][kk] = Kg[(size_t)(bk + kk) * Dm + d];
        }
        __syncthreads();

        float S[4][4] = {};
#pragma unroll
        for (int d = 0; d < 64; d++) {
            float4 q4 = *(const float4*)&Qs[d][ty * 4];
            float4 k4 = *(const float4*)&Ks[d][tx * 4];
            float qv[4] = {q4.x, q4.y, q4.z, q4.w};
            float kv[4] = {k4.x, k4.y, k4.z, k4.w};
#pragma unroll
            for (int i = 0; i < 4; i++)
#pragma unroll
                for (int j = 0; j < 4; j++)
                    S[i][j] = fmaf(qv[i], kv[j], S[i][j]);
        }
        __syncthreads();                   // done reading Ks

        // mask
#pragma unroll
        for (int i = 0; i < 4; i++) {
            int row = bq + ty * 4 + i;
            int4 m4 = *(const int4*)&mg[(size_t)row * Sq + bk + tx * 4];
            if (m4.x == 0) S[i][0] = -INFINITY;
            if (m4.y == 0) S[i][1] = -INFINITY;
            if (m4.z == 0) S[i][2] = -INFINITY;
            if (m4.w == 0) S[i][3] = -INFINITY;
        }

        // per-row chunk max across 16 tx lanes (half-warp)
        float cm[4], sc[4], cs[4];
#pragma unroll
        for (int i = 0; i < 4; i++) {
            float c = fmaxf(fmaxf(S[i][0], S[i][1]), fmaxf(S[i][2], S[i][3]));
#pragma unroll
            for (int o = 8; o; o >>= 1)
                c = fmaxf(c, __shfl_xor_sync(0xffffffffu, c, o));
            cm[i] = fmaxf(mr[i], c);
            sc[i] = __expf((mr[i] - cm[i]) * 0.125f);
            mr[i] = cm[i];
        }

        // P = exp((S - m)/8); transposed store; chunk sums
#pragma unroll
        for (int i = 0; i < 4; i++) {
            float p0 = __expf((S[i][0] - cm[i]) * 0.125f);
            float p1 = __expf((S[i][1] - cm[i]) * 0.125f);
            float p2 = __expf((S[i][2] - cm[i]) * 0.125f);
            float p3 = __expf((S[i][3] - cm[i]) * 0.125f);
            S[i][0] = p0; S[i][1] = p1; S[i][2] = p2; S[i][3] = p3;
            cs[i] = p0 + p1 + p2 + p3;
        }
#pragma unroll
        for (int i = 0; i < 4; i++) {
            float s = cs[i];
#pragma unroll
            for (int o = 8; o; o >>= 1)
                s += __shfl_xor_sync(0xffffffffu, s, o);
            lr[i] = lr[i] * sc[i] + s;
#pragma unroll
            for (int j = 0; j < 4; j++) out[i][j] *= sc[i];
        }
#pragma unroll
        for (int j = 0; j < 4; j++)        // Pst[k][q]: 4 STS.128
            *(float4*)&Pst[tx * 4 + j][ty * 4] =
                make_float4(S[0][j], S[1][j], S[2][j], S[3][j]);

#pragma unroll
        for (int l = 0; l < 16; l++) {     // Vs[k][d] into Ks
            int e = tid + l * 256;
            int kk = e >> 6, d = e & 63;
            Ks[kk][d] = Vg[(size_t)(bk + kk) * Dm + d];
        }
        __syncthreads();                   // Pst + V visible

#pragma unroll
        for (int k = 0; k < 64; k++) {
            float4 p4 = *(const float4*)&Pst[k][ty * 4];
            float4 v4 = *(const float4*)&Ks[k][tx * 4];
            float pv[4] = {p4.x, p4.y, p4.z, p4.w};
            float vv[4] = {v4.x, v4.y, v4.z, v4.w};
#pragma unroll
            for (int i = 0; i < 4; i++)
#pragma unroll
                for (int j = 0; j < 4; j++)
                    out[i][j] = fmaf(pv[i], vv[j], out[i][j]);
        }
        __syncthreads();                   // done reading Ks/Pst
    }

    // write unnormalized partials
    float* po = pout + ((size_t)(sp * 16 + z) * Sq) * DK;
#pragma unroll
    for (int i = 0; i < 4; i++) {
        int row = bq + ty * 4 + i;
        *(float4*)&po[(size_t)row * DK + tx * 4] =
            make_float4(out[i][0], out[i][1], out[i][2], out[i][3]);
        if (tx == 0) {
            float* pm = pml + ((size_t)(sp * 16 + z) * Sq) * 2;
            pm[row * 2] = mr[i]; pm[row * 2 + 1] = lr[i];
        }
    }
}

// combine NSPLIT kv-split partials -> ctx. Block (64, 4).
__global__ __launch_bounds__(256) void attn_combine(
    const float* __restrict__ pout, const float* __restrict__ pml,
    float* __restrict__ ctx)
{
    int row = blockIdx.x * 4 + threadIdx.y;   // z*Sq + q
    int d = threadIdx.x;
    int z = row >> 9, q = row & 511;
    int b = z >> 3, h = z & 7;
    float m[NSPLIT], l[NSPLIT];
    float mm = -INFINITY;
#pragma unroll
    for (int s = 0; s < NSPLIT; s++) {
        const float* pm = pml + ((size_t)(s * 16 + z) * Sq + q) * 2;
        m[s] = pm[0]; l[s] = pm[1];
        mm = fmaxf(mm, m[s]);
    }
    float lsum = 0.f, o = 0.f;
#pragma unroll
    for (int s = 0; s < NSPLIT; s++) {
        float w = __expf((m[s] - mm) * 0.125f);
        lsum = fmaf(l[s], w, lsum);
        o = fmaf(pout[((size_t)(s * 16 + z) * Sq + q) * DK + d], w, o);
    }
    ctx[(size_t)b * Sq * Dm + (size_t)q * Dm + h * DK + d] = o / lsum;
}

// ---------------- launch ----------------------------------------------------
extern "C" void kernel_launch(void* const* d_in, const int* in_sizes, int n_in,
                              void* d_out, int out_size)
{
    const float* x     = (const float*)d_in[0];
    const int*   mask  = (const int*)d_in[1];
    const float* omega = (const float*)d_in[2];
    const float* Pq    = (const float*)d_in[3];
    const float* Pk    = (const float*)d_in[4];
    const float* Pv    = (const float*)d_in[5];
    const float* Po    = (const float*)d_in[6];
    const float* tab   = (const float*)d_in[7];
    float* out = (float*)d_out;

    static int smem_set = 0;
    if (!smem_set) {
        cudaFuncSetAttribute(attn_part,
            cudaFuncAttributeMaxDynamicSharedMemorySize, ATTN_SMEM);
        smem_set = 1;
    }

    float *p_feat, *p_R, *p_Rcf, *p_qkv, *p_ctx, *p_po, *p_pm, *p_cfp, *p_cf;
    cudaGetSymbolAddress((void**)&p_feat, g_feat);
    cudaGetSymbolAddress((void**)&p_R, g_R);
    cudaGetSymbolAddress((void**)&p_Rcf, g_Rcf);
    cudaGetSymbolAddress((void**)&p_qkv, g_QKV);
    cudaGetSymbolAddress((void**)&p_ctx, g_ctx);
    cudaGetSymbolAddress((void**)&p_po, g_pout);
    cudaGetSymbolAddress((void**)&p_pm, g_pml);
    cudaGetSymbolAddress((void**)&p_cfp, g_cfp);
    cudaGetSymbolAddress((void**)&p_cf, g_cf);

    float* p_Q = p_qkv;
    float* p_K = p_qkv + (size_t)N_TOK * Dm;
    float* p_V = p_qkv + (size_t)2 * N_TOK * Dm;

    dim3 blk(16, 16);

    feat_gemm<<<dim3(2, 96), blk>>>(x, Pq, Pk, Pv, Po, omega, p_feat);
    rowrelu<<<(N_TOK + 4 * Dm) / 8, dim3(32, 8)>>>(p_feat, p_R);

    tversky_qkv<<<dim3(8, 16, 3), blk>>>(p_feat, p_R, tab, p_qkv);

    attn_part<<<dim3(8, 16, NSPLIT), blk, ATTN_SMEM>>>(p_Q, p_K, p_V, mask, p_po, p_pm);
    attn_combine<<<16 * Sq / 4, dim3(64, 4)>>>(p_po, p_pm, p_ctx);

    gemm_split<<<dim3(2, 16, 8), blk>>>(p_ctx, omega, p_cfp);
    add8<<<(N_TOK * Kf / 4) / 256, 256>>>(p_cfp, p_cf);
    rowrelu<<<N_TOK / 8, dim3(32, 8)>>>(p_cf, p_Rcf);
    tversky_out<<<dim3(8, 16), blk>>>(p_cf, p_Rcf, p_feat, p_R, tab, out);
}

// round 13
// speedup vs baseline: 1.5171x; 1.0205x over previous
#include <cuda_runtime.h>
#include <math.h>

#define N_TOK 1024
#define Dm 512
#define Kf 128
#define Sq 512
#define DK 64
#define NSPLIT 8
#define ATTN_SMEM ((64 * 132 + 64 * 68 + 128 * 68) * 4)

// ---------------- scratch ---------------------------------------------------
__device__ float g_feat[(N_TOK + 4 * Dm) * Kf];
__device__ float g_R[N_TOK + 4 * Dm];
__device__ float g_Rcf[N_TOK];
__device__ float g_QKV[3 * N_TOK * Dm];
__device__ float g_ctx[N_TOK * Dm];
__device__ float g_pout[NSPLIT * 16 * Sq * DK];
__device__ float g_pml[NSPLIT * 16 * Sq * 2];
__device__ float g_cfp[8][N_TOK * Kf];
__device__ float g_cf[N_TOK * Kf];

// ---------------- feature GEMM: feat = [x;Pq;Pk;Pv;Po] @ omega --------------
__global__ __launch_bounds__(256) void feat_gemm(
    const float* __restrict__ x,  const float* __restrict__ Pq,
    const float* __restrict__ Pk, const float* __restrict__ Pv,
    const float* __restrict__ Po, const float* __restrict__ omega,
    float* __restrict__ feat)
{
    __shared__ float As[32][36];
    __shared__ float Bs[32][68];
    int tx = threadIdx.x, ty = threadIdx.y;
    int tid = ty * 16 + tx;
    int bm = blockIdx.y * 32, bn = blockIdx.x * 64;

    const float* A;
    int row0;
    if (bm < N_TOK) { A = x; row0 = bm; }
    else {
        int s = (bm - N_TOK) >> 9;
        const float* Ps[4] = {Pq, Pk, Pv, Po};
        A = Ps[s]; row0 = (bm - N_TOK) & 511;
    }

    float acc[2][4] = {};
    for (int k0 = 0; k0 < Dm; k0 += 32) {
#pragma unroll
        for (int l = 0; l < 4; l++) {
            int e = tid + l * 256;
            int i = e >> 5, j = e & 31;
            As[j][i] = A[(size_t)(row0 + i) * Dm + k0 + j];
        }
#pragma unroll
        for (int l = 0; l < 8; l++) {
            int e = tid + l * 256;
            int kk = e >> 6, j = e & 63;
            Bs[kk][j] = omega[(size_t)(k0 + kk) * Kf + bn + j];
        }
        __syncthreads();
#pragma unroll
        for (int k = 0; k < 32; k++) {
            float2 a2 = *(const float2*)&As[k][ty * 2];
            float4 b4 = *(const float4*)&Bs[k][tx * 4];
            acc[0][0] = fmaf(a2.x, b4.x, acc[0][0]);
            acc[0][1] = fmaf(a2.x, b4.y, acc[0][1]);
            acc[0][2] = fmaf(a2.x, b4.z, acc[0][2]);
            acc[0][3] = fmaf(a2.x, b4.w, acc[0][3]);
            acc[1][0] = fmaf(a2.y, b4.x, acc[1][0]);
            acc[1][1] = fmaf(a2.y, b4.y, acc[1][1]);
            acc[1][2] = fmaf(a2.y, b4.z, acc[1][2]);
            acc[1][3] = fmaf(a2.y, b4.w, acc[1][3]);
        }
        __syncthreads();
    }
#pragma unroll
    for (int i = 0; i < 2; i++)
#pragma unroll
        for (int j = 0; j < 4; j++)
            feat[(size_t)(bm + ty * 2 + i) * Kf + bn + tx * 4 + j] = acc[i][j];
}

// ---------------- split-K GEMM (K split 8) ----------------------------------
__global__ __launch_bounds__(256) void gemm_split(
    const float* __restrict__ A, const float* __restrict__ B,
    float* __restrict__ Cp)
{
    __shared__ float As[32][68];
    __shared__ float Bs[32][68];
    int tx = threadIdx.x, ty = threadIdx.y;
    int tid = ty * 16 + tx;
    int bm = blockIdx.y * 64, bn = blockIdx.x * 64;
    int kbase = blockIdx.z * 64;
    float* C = Cp + (size_t)blockIdx.z * N_TOK * Kf;
    float acc[4][4] = {};
    for (int k0 = kbase; k0 < kbase + 64; k0 += 32) {
#pragma unroll
        for (int l = 0; l < 8; l++) {
            int e = tid + l * 256;
            int i = e >> 5, j = e & 31;
            As[j][i] = A[(size_t)(bm + i) * Dm + k0 + j];
        }
#pragma unroll
        for (int l = 0; l < 8; l++) {
            int e = tid + l * 256;
            int kk = e >> 6, j = e & 63;
            Bs[kk][j] = B[(size_t)(k0 + kk) * Kf + bn + j];
        }
        __syncthreads();
#pragma unroll
        for (int k = 0; k < 32; k++) {
            float4 a4 = *(const float4*)&As[k][ty * 4];
            float4 b4 = *(const float4*)&Bs[k][tx * 4];
            float av[4] = {a4.x, a4.y, a4.z, a4.w};
            float bv[4] = {b4.x, b4.y, b4.z, b4.w};
#pragma unroll
            for (int i = 0; i < 4; i++)
#pragma unroll
                for (int j = 0; j < 4; j++)
                    acc[i][j] = fmaf(av[i], bv[j], acc[i][j]);
        }
        __syncthreads();
    }
#pragma unroll
    for (int i = 0; i < 4; i++)
#pragma unroll
        for (int j = 0; j < 4; j++)
            C[(size_t)(bm + ty * 4 + i) * Kf + bn + tx * 4 + j] = acc[i][j];
}

// add 8 split-K partials AND emit row relu-sums (warp == one 128-float row)
__global__ __launch_bounds__(256) void add8_relu(
    const float* __restrict__ Cp, float* __restrict__ C,
    float* __restrict__ Rcf)
{
    int idx = blockIdx.x * 256 + threadIdx.x;
    const size_t n = (size_t)N_TOK * Kf;
    float4 r = ((const float4*)Cp)[idx];
#pragma unroll
    for (int z = 1; z < 8; z++) {
        float4 a = ((const float4*)(Cp + (size_t)z * n))[idx];
        r.x += a.x; r.y += a.y; r.z += a.z; r.w += a.w;
    }
    ((float4*)C)[idx] = r;
    float s = fmaxf(r.x, 0.f) + fmaxf(r.y, 0.f) + fmaxf(r.z, 0.f) + fmaxf(r.w, 0.f);
#pragma unroll
    for (int o = 16; o; o >>= 1) s += __shfl_xor_sync(0xffffffffu, s, o);
    if ((threadIdx.x & 31) == 0) Rcf[idx >> 5] = s;
}

// ---------------- row relu-sums (feat) ---------------------------------------
__global__ __launch_bounds__(256) void rowrelu(const float* __restrict__ f,
                                               float* __restrict__ R)
{
    int row = blockIdx.x * 8 + threadIdx.y;
    int lane = threadIdx.x;
    float4 v = ((const float4*)(f + (size_t)row * Kf))[lane];
    float s = fmaxf(v.x, 0.f) + fmaxf(v.y, 0.f) + fmaxf(v.z, 0.f) + fmaxf(v.w, 0.f);
#pragma unroll
    for (int o = 16; o; o >>= 1) s += __shfl_xor_sync(0xffffffffu, s, o);
    if (lane == 0) R[row] = s;
}

// ---------------- Tversky 64x64 tile, min-trick -----------------------------
__device__ __forceinline__ void tversky_tile(
    const float* __restrict__ xf, const float* __restrict__ pf,
    const float* __restrict__ Rx, const float* __restrict__ Rp,
    float th, float al, float be, int bn, int bo,
    float* __restrict__ out, int ldo)
{
    __shared__ float sxa[16][68], sxA[16][68], sxW[16][68];
    __shared__ float spa[16][68], spP[16][68], spW[16][68];
    int tx = threadIdx.x, ty = threadIdx.y;
    int tid = ty * 16 + tx;
    float acc[4][4] = {};
    for (int k0 = 0; k0 < Kf; k0 += 16) {
#pragma unroll
        for (int l = 0; l < 4; l++) {
            int e = tid + l * 256;
            int i = e >> 4, j = e & 15;
            float a = xf[(size_t)(bn + i) * Kf + k0 + j];
            sxa[j][i] = a;
            sxA[j][i] = th * fmaxf(a, 0.f);
            sxW[j][i] = (a > 0.f) ? al : 0.f;
            float p = pf[(size_t)(bo + i) * Kf + k0 + j];
            spa[j][i] = p;
            spP[j][i] = fmaxf(p, 0.f);
            spW[j][i] = (p > 0.f) ? be : 0.f;
        }
        __syncthreads();
#pragma unroll
        for (int k = 0; k < 16; k++) {
            float4 a4 = *(const float4*)&sxa[k][ty * 4];
            float4 A4 = *(const float4*)&sxA[k][ty * 4];
            float4 w4 = *(const float4*)&sxW[k][ty * 4];
            float4 p4 = *(const float4*)&spa[k][tx * 4];
            float4 P4 = *(const float4*)&spP[k][tx * 4];
            float4 v4 = *(const float4*)&spW[k][tx * 4];
            float av[4] = {a4.x, a4.y, a4.z, a4.w};
            float Av[4] = {A4.x, A4.y, A4.z, A4.w};
            float wv[4] = {w4.x, w4.y, w4.z, w4.w};
            float pv[4] = {p4.x, p4.y, p4.z, p4.w};
            float Pv[4] = {P4.x, P4.y, P4.z, P4.w};
            float vv[4] = {v4.x, v4.y, v4.z, v4.w};
#pragma unroll
            for (int i = 0; i < 4; i++)
#pragma unroll
                for (int j = 0; j < 4; j++) {
                    float m = fminf(av[i], pv[j]);
                    float t = acc[i][j];
                    t = fmaf(Av[i], Pv[j], t);
                    t = fmaf(wv[i], m, t);
                    t = fmaf(vv[j], m, t);
                    acc[i][j] = t;
                }
        }
        __syncthreads();
    }
    float rx[4], rp[4];
#pragma unroll
    for (int i = 0; i < 4; i++) rx[i] = al * Rx[bn + ty * 4 + i];
#pragma unroll
    for (int j = 0; j < 4; j++) rp[j] = be * Rp[bo + tx * 4 + j];
#pragma unroll
    for (int i = 0; i < 4; i++)
#pragma unroll
        for (int j = 0; j < 4; j++)
            out[(size_t)(bn + ty * 4 + i) * ldo + bo + tx * 4 + j] =
                acc[i][j] - rx[i] - rp[j];
}

__global__ __launch_bounds__(256) void tversky_qkv(
    const float* __restrict__ feat, const float* __restrict__ R,
    const float* __restrict__ tab, float* __restrict__ qkv)
{
    int z = blockIdx.z;
    const float* pf = feat + (size_t)(N_TOK + z * Dm) * Kf;
    const float* Rp = R + N_TOK + z * Dm;
    const float* t3 = tab + z * 3;
    float* out = qkv + (size_t)z * N_TOK * Dm;
    tversky_tile(feat, pf, R, Rp, t3[0], t3[1], t3[2],
                 blockIdx.y * 64, blockIdx.x * 64, out, Dm);
}

__global__ __launch_bounds__(256) void tversky_out(
    const float* __restrict__ cf, const float* __restrict__ Rcf,
    const float* __restrict__ feat, const float* __restrict__ R,
    const float* __restrict__ tab, float* __restrict__ out)
{
    const float* pf = feat + (size_t)(N_TOK + 3 * Dm) * Kf;
    const float* Rp = R + N_TOK + 3 * Dm;
    tversky_tile(cf, pf, Rcf, Rp, tab[9], tab[10], tab[11],
                 blockIdx.y * 64, blockIdx.x * 64, out, Dm);
}

// ---------------- flash attention v3: q-tile 128, 8q x 4k, kv-split 8 --------
// One 64-k chunk per block -> direct softmax (no online rescale).
// Broadcast Q/P operand loads keep the smem crossbar below the fma pipe.
// smem: Qs[64][132] | Ks[64][68] (K then V) | Ps[128][68]
__global__ __launch_bounds__(256, 2) void attn_part(
    const float* __restrict__ Q, const float* __restrict__ Km,
    const float* __restrict__ V, const int* __restrict__ mask,
    float* __restrict__ pout, float* __restrict__ pml)
{
    extern __shared__ float smem[];
    float (*Qs)[132] = (float (*)[132])smem;                       // [d][q]
    float (*Ks)[68]  = (float (*)[68])(smem + 64 * 132);           // [d][k] / [k][d]
    float (*Ps)[68]  = (float (*)[68])(smem + 64 * 132 + 64 * 68); // [q][k]
    int z = blockIdx.y;
    int sp = blockIdx.z;
    int b = z >> 3, h = z & 7;
    const float* Qg = Q  + (size_t)b * Sq * Dm + h * DK;
    const float* Kg = Km + (size_t)b * Sq * Dm + h * DK;
    const float* Vg = V  + (size_t)b * Sq * Dm + h * DK;
    const int*   mg = mask + (size_t)b * Sq * Sq;
    int bq = blockIdx.x * 128;
    int bk = sp * 64;
    int tx = threadIdx.x, ty = threadIdx.y;
    int tid = ty * 16 + tx;

#pragma unroll
    for (int l = 0; l < 32; l++) {         // Qs: 128q x 64d
        int e = tid + l * 256;
        int m = e >> 6, d = e & 63;
        Qs[d][m] = Qg[(size_t)(bq + m) * Dm + d];
    }
#pragma unroll
    for (int l = 0; l < 16; l++) {         // Ks[d][k]: 64 x 64
        int e = tid + l * 256;
        int kk = e >> 6, d = e & 63;
        Ks[d][kk] = Kg[(size_t)(bk + kk) * Dm + d];
    }
    __syncthreads();

    // QK: S[8][4]
    float S[8][4] = {};
#pragma unroll
    for (int d = 0; d < 64; d++) {
        float4 qa = *(const float4*)&Qs[d][ty * 8];
        float4 qb = *(const float4*)&Qs[d][ty * 8 + 4];
        float4 k4 = *(const float4*)&Ks[d][tx * 4];
        float qv[8] = {qa.x, qa.y, qa.z, qa.w, qb.x, qb.y, qb.z, qb.w};
        float kv[4] = {k4.x, k4.y, k4.z, k4.w};
#pragma unroll
        for (int i = 0; i < 8; i++)
#pragma unroll
            for (int j = 0; j < 4; j++)
                S[i][j] = fmaf(qv[i], kv[j], S[i][j]);
    }
    __syncthreads();                       // done reading Ks

    // mask
#pragma unroll
    for (int i = 0; i < 8; i++) {
        int row = bq + ty * 8 + i;
        int4 m4 = *(const int4*)&mg[(size_t)row * Sq + bk + tx * 4];
        if (m4.x == 0) S[i][0] = -INFINITY;
        if (m4.y == 0) S[i][1] = -INFINITY;
        if (m4.z == 0) S[i][2] = -INFINITY;
        if (m4.w == 0) S[i][3] = -INFINITY;
    }

    // direct softmax numerator within this chunk; (m, l) for combine
    float mr[8], lr[8];
#pragma unroll
    for (int i = 0; i < 8; i++) {
        float c = fmaxf(fmaxf(S[i][0], S[i][1]), fmaxf(S[i][2], S[i][3]));
#pragma unroll
        for (int o = 8; o; o >>= 1)
            c = fmaxf(c, __shfl_xor_sync(0xffffffffu, c, o));
        mr[i] = c;
        float p0 = __expf((S[i][0] - c) * 0.125f);
        float p1 = __expf((S[i][1] - c) * 0.125f);
        float p2 = __expf((S[i][2] - c) * 0.125f);
        float p3 = __expf((S[i][3] - c) * 0.125f);
        S[i][0] = p0; S[i][1] = p1; S[i][2] = p2; S[i][3] = p3;
        float s = p0 + p1 + p2 + p3;
#pragma unroll
        for (int o = 8; o; o >>= 1)
            s += __shfl_xor_sync(0xffffffffu, s, o);
        lr[i] = s;
    }

    // store probs [q][k]
#pragma unroll
    for (int i = 0; i < 8; i++)
        *(float4*)&Ps[ty * 8 + i][tx * 4] =
            make_float4(S[i][0], S[i][1], S[i][2], S[i][3]);

#pragma unroll
    for (int l = 0; l < 16; l++) {         // Vs[k][d] into Ks
        int e = tid + l * 256;
        int kk = e >> 6, d = e & 63;
        Ks[kk][d] = Vg[(size_t)(bk + kk) * Dm + d];
    }
    __syncthreads();

    // PV: out[8][4]; P via broadcast scalars, V via float4
    float out[8][4] = {};
#pragma unroll
    for (int k = 0; k < 64; k++) {
        float4 v4 = *(const float4*)&Ks[k][tx * 4];
        float vv[4] = {v4.x, v4.y, v4.z, v4.w};
#pragma unroll
        for (int i = 0; i < 8; i++) {
            float p = Ps[ty * 8 + i][k];
#pragma unroll
            for (int j = 0; j < 4; j++)
                out[i][j] = fmaf(p, vv[j], out[i][j]);
        }
    }

    // write unnormalized partials
    float* po = pout + ((size_t)(sp * 16 + z) * Sq) * DK;
#pragma unroll
    for (int i = 0; i < 8; i++) {
        int row = bq + ty * 8 + i;
        *(float4*)&po[(size_t)row * DK + tx * 4] =
            make_float4(out[i][0], out[i][1], out[i][2], out[i][3]);
        if (tx == 0) {
            float* pm = pml + ((size_t)(sp * 16 + z) * Sq) * 2;
            pm[row * 2] = mr[i]; pm[row * 2 + 1] = lr[i];
        }
    }
}

// combine NSPLIT kv-split partials -> ctx. Block (64, 4).
__global__ __launch_bounds__(256) void attn_combine(
    const float* __restrict__ pout, const float* __restrict__ pml,
    float* __restrict__ ctx)
{
    int row = blockIdx.x * 4 + threadIdx.y;   // z*Sq + q
    int d = threadIdx.x;
    int z = row >> 9, q = row & 511;
    int b = z >> 3, h = z & 7;
    float m[NSPLIT], l[NSPLIT];
    float mm = -INFINITY;
#pragma unroll
    for (int s = 0; s < NSPLIT; s++) {
        const float* pm = pml + ((size_t)(s * 16 + z) * Sq + q) * 2;
        m[s] = pm[0]; l[s] = pm[1];
        mm = fmaxf(mm, m[s]);
    }
    float lsum = 0.f, o = 0.f;
#pragma unroll
    for (int s = 0; s < NSPLIT; s++) {
        float w = __expf((m[s] - mm) * 0.125f);
        lsum = fmaf(l[s], w, lsum);
        o = fmaf(pout[((size_t)(s * 16 + z) * Sq + q) * DK + d], w, o);
    }
    ctx[(size_t)b * Sq * Dm + (size_t)q * Dm + h * DK + d] = o / lsum;
}

// ---------------- launch ----------------------------------------------------
extern "C" void kernel_launch(void* const* d_in, const int* in_sizes, int n_in,
                              void* d_out, int out_size)
{
    const float* x     = (const float*)d_in[0];
    const int*   mask  = (const int*)d_in[1];
    const float* omega = (const float*)d_in[2];
    const float* Pq    = (const float*)d_in[3];
    const float* Pk    = (const float*)d_in[4];
    const float* Pv    = (const float*)d_in[5];
    const float* Po    = (const float*)d_in[6];
    const float* tab   = (const float*)d_in[7];
    float* out = (float*)d_out;

    static int smem_set = 0;
    if (!smem_set) {
        cudaFuncSetAttribute(attn_part,
            cudaFuncAttributeMaxDynamicSharedMemorySize, ATTN_SMEM);
        smem_set = 1;
    }

    float *p_feat, *p_R, *p_Rcf, *p_qkv, *p_ctx, *p_po, *p_pm, *p_cfp, *p_cf;
    cudaGetSymbolAddress((void**)&p_feat, g_feat);
    cudaGetSymbolAddress((void**)&p_R, g_R);
    cudaGetSymbolAddress((void**)&p_Rcf, g_Rcf);
    cudaGetSymbolAddress((void**)&p_qkv, g_QKV);
    cudaGetSymbolAddress((void**)&p_ctx, g_ctx);
    cudaGetSymbolAddress((void**)&p_po, g_pout);
    cudaGetSymbolAddress((void**)&p_pm, g_pml);
    cudaGetSymbolAddress((void**)&p_cfp, g_cfp);
    cudaGetSymbolAddress((void**)&p_cf, g_cf);

    float* p_Q = p_qkv;
    float* p_K = p_qkv + (size_t)N_TOK * Dm;
    float* p_V = p_qkv + (size_t)2 * N_TOK * Dm;

    dim3 blk(16, 16);

    feat_gemm<<<dim3(2, 96), blk>>>(x, Pq, Pk, Pv, Po, omega, p_feat);
    rowrelu<<<(N_TOK + 4 * Dm) / 8, dim3(32, 8)>>>(p_feat, p_R);

    tversky_qkv<<<dim3(8, 16, 3), blk>>>(p_feat, p_R, tab, p_qkv);

    attn_part<<<dim3(4, 16, NSPLIT), blk, ATTN_SMEM>>>(p_Q, p_K, p_V, mask, p_po, p_pm);
    attn_combine<<<16 * Sq / 4, dim3(64, 4)>>>(p_po, p_pm, p_ctx);

    gemm_split<<<dim3(2, 16, 8), blk>>>(p_ctx, omega, p_cfp);
    add8_relu<<<(N_TOK * Kf / 4) / 256, 256>>>(p_cfp, p_cf, p_Rcf);
    tversky_out<<<dim3(8, 16), blk>>>(p_cf, p_Rcf, p_feat, p_R, tab, out);
}